// round 1
// baseline (speedup 1.0000x reference)
#include <cuda_runtime.h>
#include <cstddef>

// Problem constants
#define B_  8
#define T_  1024
#define E_  1024
#define H_  16
#define DH_ 64
#define M_TOK (B_ * T_)        // 8192 tokens

// ---------------------------------------------------------------------------
// Scratch (no cudaMalloc allowed -> __device__ globals)
// ---------------------------------------------------------------------------
__device__ float g_qkv[(size_t)M_TOK * 3 * E_];   // 96 MB
__device__ float g_att[(size_t)M_TOK * E_];       // 32 MB
__device__ float g_tmp[(size_t)M_TOK * E_];       // 32 MB

// ---------------------------------------------------------------------------
// NT SGEMM with bias: C[M,N] = A[M,K] * B[N,K]^T + bias[N]
// All row-major. Requires M%128==0, N%128==0, K%16==0.
// BM=BN=128, BK=16, 256 threads, 8x8 per-thread micro-tile.
// ---------------------------------------------------------------------------
#define BM 128
#define BN 128
#define BK 16

__global__ __launch_bounds__(256, 2)
void sgemm_nt_bias(const float* __restrict__ A,
                   const float* __restrict__ Bm,
                   const float* __restrict__ bias,
                   float* __restrict__ C,
                   int M, int N, int K)
{
    __shared__ float As[BK][BM + 4];
    __shared__ float Bs[BK][BN + 4];

    const int bx = blockIdx.x;           // N tile
    const int by = blockIdx.y;           // M tile
    const int tid = threadIdx.x;
    const int tx = tid % 16;             // 0..15  -> n micro
    const int ty = tid / 16;             // 0..15  -> m micro

    const float* Ab = A + (size_t)by * BM * K;
    const float* Bb = Bm + (size_t)bx * BN * K;

    const int l_row  = tid >> 2;         // 0..63
    const int l_col4 = (tid & 3) * 4;    // 0,4,8,12

    float acc[8][8];
#pragma unroll
    for (int i = 0; i < 8; i++)
#pragma unroll
        for (int j = 0; j < 8; j++) acc[i][j] = 0.f;

    for (int k0 = 0; k0 < K; k0 += BK) {
        // load A tile (128 x 16), transpose into As[k][m]
#pragma unroll
        for (int u = 0; u < 2; u++) {
            int r = l_row + u * 64;
            float4 v = *(const float4*)(Ab + (size_t)r * K + k0 + l_col4);
            As[l_col4 + 0][r] = v.x;
            As[l_col4 + 1][r] = v.y;
            As[l_col4 + 2][r] = v.z;
            As[l_col4 + 3][r] = v.w;
        }
        // load B tile (128 x 16), transpose into Bs[k][n]
#pragma unroll
        for (int u = 0; u < 2; u++) {
            int r = l_row + u * 64;
            float4 v = *(const float4*)(Bb + (size_t)r * K + k0 + l_col4);
            Bs[l_col4 + 0][r] = v.x;
            Bs[l_col4 + 1][r] = v.y;
            Bs[l_col4 + 2][r] = v.z;
            Bs[l_col4 + 3][r] = v.w;
        }
        __syncthreads();

#pragma unroll
        for (int k = 0; k < BK; k++) {
            float4 a0 = *(const float4*)(&As[k][ty * 8]);
            float4 a1 = *(const float4*)(&As[k][ty * 8 + 4]);
            float4 b0 = *(const float4*)(&Bs[k][tx * 8]);
            float4 b1 = *(const float4*)(&Bs[k][tx * 8 + 4]);
            float ar[8] = {a0.x, a0.y, a0.z, a0.w, a1.x, a1.y, a1.z, a1.w};
            float br[8] = {b0.x, b0.y, b0.z, b0.w, b1.x, b1.y, b1.z, b1.w};
#pragma unroll
            for (int i = 0; i < 8; i++)
#pragma unroll
                for (int j = 0; j < 8; j++)
                    acc[i][j] = fmaf(ar[i], br[j], acc[i][j]);
        }
        __syncthreads();
    }

    // epilogue: + bias, vectorized store
    const int n0 = bx * BN + tx * 8;
    float4 bb0 = *(const float4*)(bias + n0);
    float4 bb1 = *(const float4*)(bias + n0 + 4);
#pragma unroll
    for (int i = 0; i < 8; i++) {
        size_t row = (size_t)(by * BM + ty * 8 + i) * N + n0;
        float4 c0, c1;
        c0.x = acc[i][0] + bb0.x; c0.y = acc[i][1] + bb0.y;
        c0.z = acc[i][2] + bb0.z; c0.w = acc[i][3] + bb0.w;
        c1.x = acc[i][4] + bb1.x; c1.y = acc[i][5] + bb1.y;
        c1.z = acc[i][6] + bb1.z; c1.w = acc[i][7] + bb1.w;
        *(float4*)(C + row)     = c0;
        *(float4*)(C + row + 4) = c1;
    }
}

// ---------------------------------------------------------------------------
// Fused causal flash attention (fp32).
// qkv: [B, T, 3E], layout per token: [Q(E) | K(E) | V(E)], head h = cols h*64..h*64+63
// out: [B, T, E] with out[b,t,h*64+d] = softmax(QK^T/sqrt(64)) V
// grid: (T/64, B*H), block: 256 threads.
// ---------------------------------------------------------------------------
__global__ __launch_bounds__(256, 2)
void attn_kernel(const float* __restrict__ qkv, float* __restrict__ out)
{
    extern __shared__ float sm[];
    float* Qs  = sm;             // [64][64]  d-major: Qs[d*64 + i]
    float* KPs = Qs + 64 * 64;   // K d-major Ks[d*64+j]; reused as P[j*64+i]
    float* Vs  = KPs + 64 * 64;  // [j][d] row-major
    float* red = Vs + 64 * 64;   // [4][64] partial reductions
    float* mrow = red + 4 * 64;  // [64]
    float* lrow = mrow + 64;     // [64]
    float* arow = lrow + 64;     // [64]

    const int qt  = blockIdx.x;          // query tile 0..15
    const int bh  = blockIdx.y;          // 0..127
    const int b   = bh / H_;
    const int h   = bh % H_;
    const int tid = threadIdx.x;
    const int tx  = tid % 16;            // key / d micro col (x4)
    const int ty  = tid / 16;            // query micro row (x4)

    const size_t rs = 3 * E_;            // token stride in qkv
    const float* base = qkv + (size_t)b * T_ * rs;
    const int qoff = h * DH_;
    const int koff = E_ + h * DH_;
    const int voff = 2 * E_ + h * DH_;

    // load Q tile, transposed to d-major
    {
        const int i  = tid >> 2;          // 0..63 (token row)
        const int d4 = (tid & 3) * 16;    // 16 floats along d
        const float* qrow = base + (size_t)(qt * 64 + i) * rs + qoff;
#pragma unroll
        for (int u = 0; u < 4; u++) {
            float4 v = *(const float4*)(qrow + d4 + u * 4);
            int d = d4 + u * 4;
            Qs[(d + 0) * 64 + i] = v.x;
            Qs[(d + 1) * 64 + i] = v.y;
            Qs[(d + 2) * 64 + i] = v.z;
            Qs[(d + 3) * 64 + i] = v.w;
        }
    }
    if (tid < 64) { mrow[tid] = -1e30f; lrow[tid] = 0.f; }

    float Oacc[4][4];
#pragma unroll
    for (int i = 0; i < 4; i++)
#pragma unroll
        for (int j = 0; j < 4; j++) Oacc[i][j] = 0.f;

    __syncthreads();

    for (int kt = 0; kt <= qt; kt++) {
        // load K (d-major) and V (row-major) tiles
        {
            const int j  = tid >> 2;
            const int d4 = (tid & 3) * 16;
            const float* krow = base + (size_t)(kt * 64 + j) * rs + koff;
            const float* vrow = base + (size_t)(kt * 64 + j) * rs + voff;
#pragma unroll
            for (int u = 0; u < 4; u++) {
                int d = d4 + u * 4;
                float4 kv = *(const float4*)(krow + d);
                KPs[(d + 0) * 64 + j] = kv.x;
                KPs[(d + 1) * 64 + j] = kv.y;
                KPs[(d + 2) * 64 + j] = kv.z;
                KPs[(d + 3) * 64 + j] = kv.w;
                *(float4*)(Vs + j * 64 + d) = *(const float4*)(vrow + d);
            }
        }
        __syncthreads();

        // S = Q K^T : thread owns rows qi=ty*4.., cols kj=tx*4..
        float S[4][4];
#pragma unroll
        for (int i = 0; i < 4; i++)
#pragma unroll
            for (int j = 0; j < 4; j++) S[i][j] = 0.f;

#pragma unroll 8
        for (int d = 0; d < 64; d++) {
            float4 a = *(const float4*)(Qs + d * 64 + ty * 4);
            float4 c = *(const float4*)(KPs + d * 64 + tx * 4);
            float ar[4] = {a.x, a.y, a.z, a.w};
            float cr[4] = {c.x, c.y, c.z, c.w};
#pragma unroll
            for (int i = 0; i < 4; i++)
#pragma unroll
                for (int j = 0; j < 4; j++)
                    S[i][j] = fmaf(ar[i], cr[j], S[i][j]);
        }

        // scale + causal mask
        const float scale = 0.125f;          // 1/sqrt(64)
        const int qg0 = qt * 64 + ty * 4;
        const int kg0 = kt * 64 + tx * 4;
#pragma unroll
        for (int i = 0; i < 4; i++)
#pragma unroll
            for (int j = 0; j < 4; j++) {
                float s = S[i][j] * scale;
                if (kg0 + j > qg0 + i) s = -1e30f;
                S[i][j] = s;
            }

        __syncthreads();   // everyone done reading K before we overwrite KPs

        // write S transposed: P-buffer layout [j][i]
#pragma unroll
        for (int j = 0; j < 4; j++)
#pragma unroll
            for (int i = 0; i < 4; i++)
                KPs[(tx * 4 + j) * 64 + (ty * 4 + i)] = S[i][j];
        __syncthreads();

        // partial row max
        {
            const int i = tid & 63, g = tid >> 6;
            float pm = -1e30f;
#pragma unroll 4
            for (int j = g * 16; j < g * 16 + 16; j++)
                pm = fmaxf(pm, KPs[j * 64 + i]);
            red[g * 64 + i] = pm;
        }
        __syncthreads();
        if (tid < 64) {
            float mo = mrow[tid];
            float mn = fmaxf(fmaxf(red[tid], red[64 + tid]),
                             fmaxf(red[128 + tid], red[192 + tid]));
            mn = fmaxf(mn, mo);
            mrow[tid] = mn;
            arow[tid] = __expf(mo - mn);
        }
        __syncthreads();
        // exponentiate in place + partial row sums
        {
            const int i = tid & 63, g = tid >> 6;
            const float mn = mrow[i];
            float ps = 0.f;
#pragma unroll 4
            for (int j = g * 16; j < g * 16 + 16; j++) {
                float p = __expf(KPs[j * 64 + i] - mn);
                KPs[j * 64 + i] = p;
                ps += p;
            }
            red[g * 64 + i] = ps;
        }
        __syncthreads();
        if (tid < 64)
            lrow[tid] = lrow[tid] * arow[tid]
                      + red[tid] + red[64 + tid] + red[128 + tid] + red[192 + tid];

        // rescale O by alpha, accumulate P V
#pragma unroll
        for (int i = 0; i < 4; i++) {
            float al = arow[ty * 4 + i];
#pragma unroll
            for (int dd = 0; dd < 4; dd++) Oacc[i][dd] *= al;
        }
#pragma unroll 8
        for (int j = 0; j < 64; j++) {
            float4 p = *(const float4*)(KPs + j * 64 + ty * 4);
            float4 v = *(const float4*)(Vs  + j * 64 + tx * 4);
            float pr[4] = {p.x, p.y, p.z, p.w};
            float vr[4] = {v.x, v.y, v.z, v.w};
#pragma unroll
            for (int i = 0; i < 4; i++)
#pragma unroll
                for (int dd = 0; dd < 4; dd++)
                    Oacc[i][dd] = fmaf(pr[i], vr[dd], Oacc[i][dd]);
        }
        __syncthreads();   // protect KPs/Vs before next tile load
    }

    // epilogue: normalize rows and store to [B,T,E]
#pragma unroll
    for (int i = 0; i < 4; i++) {
        const int qg = qt * 64 + ty * 4 + i;
        float inv = 1.f / lrow[ty * 4 + i];
        float4 o;
        o.x = Oacc[i][0] * inv;
        o.y = Oacc[i][1] * inv;
        o.z = Oacc[i][2] * inv;
        o.w = Oacc[i][3] * inv;
        *(float4*)(out + (size_t)(b * T_ + qg) * E_ + h * DH_ + tx * 4) = o;
    }
}

// ---------------------------------------------------------------------------
// kernel_launch
// inputs (metadata order): x, in_proj_w, in_proj_b, out_proj_w, out_proj_b,
//                          c_proj_w, c_proj_b
// ---------------------------------------------------------------------------
extern "C" void kernel_launch(void* const* d_in, const int* in_sizes, int n_in,
                              void* d_out, int out_size)
{
    const float* x     = (const float*)d_in[0];
    const float* w_in  = (const float*)d_in[1];
    const float* b_in  = (const float*)d_in[2];
    const float* w_out = (const float*)d_in[3];
    const float* b_out = (const float*)d_in[4];
    const float* w_c   = (const float*)d_in[5];
    const float* b_c   = (const float*)d_in[6];
    float* out = (float*)d_out;

    float *qkv, *att, *tmp;
    cudaGetSymbolAddress((void**)&qkv, g_qkv);
    cudaGetSymbolAddress((void**)&att, g_att);
    cudaGetSymbolAddress((void**)&tmp, g_tmp);

    // 1) fused QKV projection: [8192,1024] x [3072,1024]^T
    sgemm_nt_bias<<<dim3(3 * E_ / BN, M_TOK / BM), 256>>>(
        x, w_in, b_in, qkv, M_TOK, 3 * E_, E_);

    // 2) causal flash attention
    const size_t attn_smem = (3 * 64 * 64 + 4 * 64 + 3 * 64) * sizeof(float);
    cudaFuncSetAttribute(attn_kernel,
                         cudaFuncAttributeMaxDynamicSharedMemorySize,
                         (int)attn_smem);
    attn_kernel<<<dim3(T_ / 64, B_ * H_), 256, attn_smem>>>(qkv, att);

    // 3) out_proj
    sgemm_nt_bias<<<dim3(E_ / BN, M_TOK / BM), 256>>>(
        att, w_out, b_out, tmp, M_TOK, E_, E_);

    // 4) c_proj
    sgemm_nt_bias<<<dim3(E_ / BN, M_TOK / BM), 256>>>(
        tmp, w_c, b_c, out, M_TOK, E_, E_);
}

// round 3
// speedup vs baseline: 1.5816x; 1.5816x over previous
#include <cuda_runtime.h>
#include <cuda_bf16.h>
#include <cstdint>
#include <cstddef>

// Problem constants
#define B_  8
#define T_  1024
#define E_  1024
#define H_  16
#define DH_ 64
#define M_TOK (B_ * T_)        // 8192 tokens

// ---------------------------------------------------------------------------
// Scratch (no cudaMalloc allowed -> __device__ globals)
// ---------------------------------------------------------------------------
__device__ float g_qkv[(size_t)M_TOK * 3 * E_];            // 96 MB
__device__ float g_att[(size_t)M_TOK * E_];                // 32 MB
__device__ float g_tmp[(size_t)M_TOK * E_];                // 32 MB
__device__ __nv_bfloat16 g_ah[(size_t)M_TOK * E_];         // 16 MB (activation hi)
__device__ __nv_bfloat16 g_al[(size_t)M_TOK * E_];         // 16 MB (activation lo)
__device__ __nv_bfloat16 g_wh[(size_t)3 * E_ * E_];        // 6 MB  (weight hi)
__device__ __nv_bfloat16 g_wl[(size_t)3 * E_ * E_];        // 6 MB  (weight lo)

// ---------------------------------------------------------------------------
// PTX helpers (portable: sm_80+ instructions only; target is base sm_100)
// ---------------------------------------------------------------------------
__device__ __forceinline__ uint32_t smem_to_u32(const void* p) {
    uint32_t a;
    asm("{ .reg .u64 t; cvta.to.shared.u64 t, %1; cvt.u32.u64 %0, t; }"
        : "=r"(a) : "l"(p));
    return a;
}

#define CP_ASYNC16(dst, src) \
    asm volatile("cp.async.cg.shared.global [%0], [%1], 16;" \
                 :: "r"(dst), "l"(src) : "memory")
#define CP_COMMIT() asm volatile("cp.async.commit_group;" ::: "memory")
#define CP_WAIT(n)  asm volatile("cp.async.wait_group %0;" :: "n"(n) : "memory")

#define LDSM_X4(r, addr) \
    asm volatile("ldmatrix.sync.aligned.m8n8.x4.shared.b16 {%0,%1,%2,%3}, [%4];" \
                 : "=r"((r)[0]), "=r"((r)[1]), "=r"((r)[2]), "=r"((r)[3]) \
                 : "r"(addr))
#define LDSM_X2(r, addr) \
    asm volatile("ldmatrix.sync.aligned.m8n8.x2.shared.b16 {%0,%1}, [%2];" \
                 : "=r"((r)[0]), "=r"((r)[1]) : "r"(addr))

#define MMA_BF16(c, a, b) \
    asm volatile("mma.sync.aligned.m16n8k16.row.col.f32.bf16.bf16.f32 " \
                 "{%0,%1,%2,%3}, {%4,%5,%6,%7}, {%8,%9}, {%0,%1,%2,%3};" \
                 : "+f"((c)[0]), "+f"((c)[1]), "+f"((c)[2]), "+f"((c)[3]) \
                 : "r"((a)[0]), "r"((a)[1]), "r"((a)[2]), "r"((a)[3]), \
                   "r"((b)[0]), "r"((b)[1]))

// ---------------------------------------------------------------------------
// fp32 -> (bf16 hi, bf16 lo) split, vectorized
// ---------------------------------------------------------------------------
__device__ __forceinline__ uint32_t pack_bf(__nv_bfloat16 a, __nv_bfloat16 b) {
    __nv_bfloat162 t = __halves2bfloat162(a, b);
    return *reinterpret_cast<uint32_t*>(&t);
}

__global__ void split_kernel(const float* __restrict__ x,
                             __nv_bfloat16* __restrict__ hi,
                             __nv_bfloat16* __restrict__ lo, int n4) {
    int i = blockIdx.x * blockDim.x + threadIdx.x;
    int stride = gridDim.x * blockDim.x;
    for (; i < n4; i += stride) {
        float4 v = ((const float4*)x)[i];
        __nv_bfloat16 h0 = __float2bfloat16_rn(v.x);
        __nv_bfloat16 h1 = __float2bfloat16_rn(v.y);
        __nv_bfloat16 h2 = __float2bfloat16_rn(v.z);
        __nv_bfloat16 h3 = __float2bfloat16_rn(v.w);
        __nv_bfloat16 l0 = __float2bfloat16_rn(v.x - __bfloat162float(h0));
        __nv_bfloat16 l1 = __float2bfloat16_rn(v.y - __bfloat162float(h1));
        __nv_bfloat16 l2 = __float2bfloat16_rn(v.z - __bfloat162float(h2));
        __nv_bfloat16 l3 = __float2bfloat16_rn(v.w - __bfloat162float(h3));
        ((uint2*)hi)[i] = make_uint2(pack_bf(h0, h1), pack_bf(h2, h3));
        ((uint2*)lo)[i] = make_uint2(pack_bf(l0, l1), pack_bf(l2, l3));
    }
}

// ---------------------------------------------------------------------------
// mma.sync bf16 split GEMM: C[M,N] = Ah*Bh^T + Ah*Bl^T + Al*Bh^T + bias
// A: [M,K] bf16 row-major (hi/lo). B: [N,K] bf16 row-major (hi/lo).
// Block 128x128, 8 warps (2x4 of 64x32), KC=32, double-buffered cp.async.
// smem stage layout: Ah[128][32] | Al | Bh | Bl  (8 KB each, 32 KB/stage).
// smem swizzle: 16B unit index ^= (row>>1)&3  (64B rows, ldmatrix conflict-free)
// ---------------------------------------------------------------------------
#define KC 32
#define STAGE_B 32768
#define GEMM_SMEM (2 * STAGE_B)

__global__ __launch_bounds__(256)
void gemm_mma_split(const __nv_bfloat16* __restrict__ Ah,
                    const __nv_bfloat16* __restrict__ Al,
                    const __nv_bfloat16* __restrict__ Bh,
                    const __nv_bfloat16* __restrict__ Bl,
                    const float* __restrict__ bias,
                    float* __restrict__ C,
                    int M, int N, int K)
{
    extern __shared__ char smem[];
    const uint32_t sbase = smem_to_u32(smem);
    const int tid  = threadIdx.x;
    const int wid  = tid >> 5;
    const int lane = tid & 31;
    const int warpM = (wid >> 2) * 64;   // 0 or 64
    const int warpN = (wid & 3) * 32;    // 0,32,64,96
    const int rowA = blockIdx.y * 128;
    const int rowB = blockIdx.x * 128;

    float acc[4][4][4];
#pragma unroll
    for (int mt = 0; mt < 4; mt++)
#pragma unroll
        for (int nt = 0; nt < 4; nt++)
#pragma unroll
            for (int r = 0; r < 4; r++) acc[mt][nt][r] = 0.f;

    // per-thread load mapping (2 x 16B per operand per stage)
    const int idx0 = tid * 2;

    const int NC = K / KC;

    // ---- stage loader ----
    auto load_stage = [&](int c, int s) {
        const uint32_t sb = sbase + s * STAGE_B;
#pragma unroll
        for (int e = 0; e < 2; e++) {
            int idx  = idx0 + e;
            int row  = idx >> 2;          // 0..127
            int unit = idx & 3;           // 16B unit in 64B row
            uint32_t soff = (uint32_t)(row * 64 + ((unit ^ ((row >> 1) & 3)) << 4));
            size_t goffA = ((size_t)(rowA + row) * K + c * KC + unit * 8) * 2;
            size_t goffB = ((size_t)(rowB + row) * K + c * KC + unit * 8) * 2;
            CP_ASYNC16(sb + soff,         (const char*)Ah + goffA);
            CP_ASYNC16(sb +  8192 + soff, (const char*)Al + goffA);
            CP_ASYNC16(sb + 16384 + soff, (const char*)Bh + goffB);
            CP_ASYNC16(sb + 24576 + soff, (const char*)Bl + goffB);
        }
    };

    load_stage(0, 0);
    CP_COMMIT();

    // ldmatrix per-lane address components
    const int a_row_in = (lane & 7) + ((lane >> 3) & 1) * 8;   // 0..15
    const int a_ksub   = (lane >> 4);                          // 0/1 (8-elem unit)
    const int tl       = lane & 15;
    const int b_row_in = tl & 7;
    const int b_ksub   = (tl >> 3) & 1;

    for (int c = 0; c < NC; c++) {
        if (c + 1 < NC) {
            load_stage(c + 1, (c + 1) & 1);
            CP_COMMIT();
            CP_WAIT(1);
        } else {
            CP_WAIT(0);
        }
        __syncthreads();

        const uint32_t sb = sbase + (c & 1) * STAGE_B;

        // 3 operand pairs: (Ah,Bh), (Ah,Bl), (Al,Bh)
#pragma unroll
        for (int p = 0; p < 3; p++) {
            const uint32_t abase = sb + (p == 2 ? 8192 : 0);
            const uint32_t bbase = sb + 16384 + (p == 1 ? 8192 : 0);
#pragma unroll
            for (int j = 0; j < 2; j++) {       // two k16 steps in KC=32
                uint32_t a[4][4];
                uint32_t b[4][2];
                const int aunit = j * 2 + a_ksub;
                const int bunit = j * 2 + b_ksub;
#pragma unroll
                for (int mt = 0; mt < 4; mt++) {
                    int row = warpM + mt * 16 + a_row_in;
                    uint32_t addr = abase + row * 64 +
                                    ((aunit ^ ((row >> 1) & 3)) << 4);
                    LDSM_X4(a[mt], addr);
                }
#pragma unroll
                for (int nt = 0; nt < 4; nt++) {
                    int row = warpN + nt * 8 + b_row_in;
                    uint32_t addr = bbase + row * 64 +
                                    ((bunit ^ ((row >> 1) & 3)) << 4);
                    LDSM_X2(b[nt], addr);
                }
#pragma unroll
                for (int mt = 0; mt < 4; mt++)
#pragma unroll
                    for (int nt = 0; nt < 4; nt++)
                        MMA_BF16(acc[mt][nt], a[mt], b[nt]);
            }
        }
        __syncthreads();
    }

    // ---- epilogue: + bias, fp32 stores ----
    const int erow = lane >> 2;          // 0..7
    const int ecol = (lane & 3) * 2;     // 0,2,4,6
#pragma unroll
    for (int mt = 0; mt < 4; mt++) {
#pragma unroll
        for (int nt = 0; nt < 4; nt++) {
            int gr = rowA + warpM + mt * 16 + erow;
            int gc = rowB + warpN + nt * 8 + ecol;   // rowB == N-tile origin
            float b0 = __ldg(bias + gc);
            float b1 = __ldg(bias + gc + 1);
            float2 v0 = make_float2(acc[mt][nt][0] + b0, acc[mt][nt][1] + b1);
            float2 v1 = make_float2(acc[mt][nt][2] + b0, acc[mt][nt][3] + b1);
            *(float2*)(C + (size_t)gr * N + gc)       = v0;
            *(float2*)(C + (size_t)(gr + 8) * N + gc) = v1;
        }
    }
}

// ---------------------------------------------------------------------------
// Fused causal flash attention (fp32) — unchanged (passing, ~500us).
// ---------------------------------------------------------------------------
__global__ __launch_bounds__(256, 2)
void attn_kernel(const float* __restrict__ qkv, float* __restrict__ out)
{
    extern __shared__ float sm[];
    float* Qs  = sm;
    float* KPs = Qs + 64 * 64;
    float* Vs  = KPs + 64 * 64;
    float* red = Vs + 64 * 64;
    float* mrow = red + 4 * 64;
    float* lrow = mrow + 64;
    float* arow = lrow + 64;

    const int qt  = blockIdx.x;
    const int bh  = blockIdx.y;
    const int b   = bh / H_;
    const int h   = bh % H_;
    const int tid = threadIdx.x;
    const int tx  = tid % 16;
    const int ty  = tid / 16;

    const size_t rs = 3 * E_;
    const float* base = qkv + (size_t)b * T_ * rs;
    const int qoff = h * DH_;
    const int koff = E_ + h * DH_;
    const int voff = 2 * E_ + h * DH_;

    {
        const int i  = tid >> 2;
        const int d4 = (tid & 3) * 16;
        const float* qrow = base + (size_t)(qt * 64 + i) * rs + qoff;
#pragma unroll
        for (int u = 0; u < 4; u++) {
            float4 v = *(const float4*)(qrow + d4 + u * 4);
            int d = d4 + u * 4;
            Qs[(d + 0) * 64 + i] = v.x;
            Qs[(d + 1) * 64 + i] = v.y;
            Qs[(d + 2) * 64 + i] = v.z;
            Qs[(d + 3) * 64 + i] = v.w;
        }
    }
    if (tid < 64) { mrow[tid] = -1e30f; lrow[tid] = 0.f; }

    float Oacc[4][4];
#pragma unroll
    for (int i = 0; i < 4; i++)
#pragma unroll
        for (int j = 0; j < 4; j++) Oacc[i][j] = 0.f;

    __syncthreads();

    for (int kt = 0; kt <= qt; kt++) {
        {
            const int j  = tid >> 2;
            const int d4 = (tid & 3) * 16;
            const float* krow = base + (size_t)(kt * 64 + j) * rs + koff;
            const float* vrow = base + (size_t)(kt * 64 + j) * rs + voff;
#pragma unroll
            for (int u = 0; u < 4; u++) {
                int d = d4 + u * 4;
                float4 kv = *(const float4*)(krow + d);
                KPs[(d + 0) * 64 + j] = kv.x;
                KPs[(d + 1) * 64 + j] = kv.y;
                KPs[(d + 2) * 64 + j] = kv.z;
                KPs[(d + 3) * 64 + j] = kv.w;
                *(float4*)(Vs + j * 64 + d) = *(const float4*)(vrow + d);
            }
        }
        __syncthreads();

        float S[4][4];
#pragma unroll
        for (int i = 0; i < 4; i++)
#pragma unroll
            for (int j = 0; j < 4; j++) S[i][j] = 0.f;

#pragma unroll 8
        for (int d = 0; d < 64; d++) {
            float4 a = *(const float4*)(Qs + d * 64 + ty * 4);
            float4 c = *(const float4*)(KPs + d * 64 + tx * 4);
            float ar[4] = {a.x, a.y, a.z, a.w};
            float cr[4] = {c.x, c.y, c.z, c.w};
#pragma unroll
            for (int i = 0; i < 4; i++)
#pragma unroll
                for (int j = 0; j < 4; j++)
                    S[i][j] = fmaf(ar[i], cr[j], S[i][j]);
        }

        const float scale = 0.125f;
        const int qg0 = qt * 64 + ty * 4;
        const int kg0 = kt * 64 + tx * 4;
#pragma unroll
        for (int i = 0; i < 4; i++)
#pragma unroll
            for (int j = 0; j < 4; j++) {
                float s = S[i][j] * scale;
                if (kg0 + j > qg0 + i) s = -1e30f;
                S[i][j] = s;
            }

        __syncthreads();

#pragma unroll
        for (int j = 0; j < 4; j++)
#pragma unroll
            for (int i = 0; i < 4; i++)
                KPs[(tx * 4 + j) * 64 + (ty * 4 + i)] = S[i][j];
        __syncthreads();

        {
            const int i = tid & 63, g = tid >> 6;
            float pm = -1e30f;
#pragma unroll 4
            for (int j = g * 16; j < g * 16 + 16; j++)
                pm = fmaxf(pm, KPs[j * 64 + i]);
            red[g * 64 + i] = pm;
        }
        __syncthreads();
        if (tid < 64) {
            float mo = mrow[tid];
            float mn = fmaxf(fmaxf(red[tid], red[64 + tid]),
                             fmaxf(red[128 + tid], red[192 + tid]));
            mn = fmaxf(mn, mo);
            mrow[tid] = mn;
            arow[tid] = __expf(mo - mn);
        }
        __syncthreads();
        {
            const int i = tid & 63, g = tid >> 6;
            const float mn = mrow[i];
            float ps = 0.f;
#pragma unroll 4
            for (int j = g * 16; j < g * 16 + 16; j++) {
                float p = __expf(KPs[j * 64 + i] - mn);
                KPs[j * 64 + i] = p;
                ps += p;
            }
            red[g * 64 + i] = ps;
        }
        __syncthreads();
        if (tid < 64)
            lrow[tid] = lrow[tid] * arow[tid]
                      + red[tid] + red[64 + tid] + red[128 + tid] + red[192 + tid];

#pragma unroll
        for (int i = 0; i < 4; i++) {
            float al = arow[ty * 4 + i];
#pragma unroll
            for (int dd = 0; dd < 4; dd++) Oacc[i][dd] *= al;
        }
#pragma unroll 8
        for (int j = 0; j < 64; j++) {
            float4 p = *(const float4*)(KPs + j * 64 + ty * 4);
            float4 v = *(const float4*)(Vs  + j * 64 + tx * 4);
            float pr[4] = {p.x, p.y, p.z, p.w};
            float vr[4] = {v.x, v.y, v.z, v.w};
#pragma unroll
            for (int i = 0; i < 4; i++)
#pragma unroll
                for (int dd = 0; dd < 4; dd++)
                    Oacc[i][dd] = fmaf(pr[i], vr[dd], Oacc[i][dd]);
        }
        __syncthreads();
    }

#pragma unroll
    for (int i = 0; i < 4; i++) {
        const int qg = qt * 64 + ty * 4 + i;
        float inv = 1.f / lrow[ty * 4 + i];
        float4 o;
        o.x = Oacc[i][0] * inv;
        o.y = Oacc[i][1] * inv;
        o.z = Oacc[i][2] * inv;
        o.w = Oacc[i][3] * inv;
        *(float4*)(out + (size_t)(b * T_ + qg) * E_ + h * DH_ + tx * 4) = o;
    }
}

// ---------------------------------------------------------------------------
// kernel_launch
// inputs: x, in_proj_w, in_proj_b, out_proj_w, out_proj_b, c_proj_w, c_proj_b
// ---------------------------------------------------------------------------
extern "C" void kernel_launch(void* const* d_in, const int* in_sizes, int n_in,
                              void* d_out, int out_size)
{
    const float* x     = (const float*)d_in[0];
    const float* w_in  = (const float*)d_in[1];
    const float* b_in  = (const float*)d_in[2];
    const float* w_out = (const float*)d_in[3];
    const float* b_out = (const float*)d_in[4];
    const float* w_c   = (const float*)d_in[5];
    const float* b_c   = (const float*)d_in[6];
    float* out = (float*)d_out;

    float *qkv, *att, *tmp;
    __nv_bfloat16 *ah, *al, *wh, *wl;
    cudaGetSymbolAddress((void**)&qkv, g_qkv);
    cudaGetSymbolAddress((void**)&att, g_att);
    cudaGetSymbolAddress((void**)&tmp, g_tmp);
    cudaGetSymbolAddress((void**)&ah, g_ah);
    cudaGetSymbolAddress((void**)&al, g_al);
    cudaGetSymbolAddress((void**)&wh, g_wh);
    cudaGetSymbolAddress((void**)&wl, g_wl);

    cudaFuncSetAttribute(gemm_mma_split,
                         cudaFuncAttributeMaxDynamicSharedMemorySize, GEMM_SMEM);

    const int NA4   = M_TOK * E_ / 4;
    const int NWIN4 = 3 * E_ * E_ / 4;
    const int NW4   = E_ * E_ / 4;

    // 1) split x and in_proj_w to bf16 hi/lo
    split_kernel<<<1024, 256>>>(x, ah, al, NA4);
    split_kernel<<<1024, 256>>>(w_in, wh, wl, NWIN4);

    // 2) QKV GEMM: [8192,1024] x [3072,1024]^T -> [8192,3072]
    gemm_mma_split<<<dim3(3 * E_ / 128, M_TOK / 128), 256, GEMM_SMEM>>>(
        ah, al, wh, wl, b_in, qkv, M_TOK, 3 * E_, E_);

    // 3) causal flash attention
    const size_t attn_smem = (3 * 64 * 64 + 4 * 64 + 3 * 64) * sizeof(float);
    cudaFuncSetAttribute(attn_kernel,
                         cudaFuncAttributeMaxDynamicSharedMemorySize,
                         (int)attn_smem);
    attn_kernel<<<dim3(T_ / 64, B_ * H_), 256, attn_smem>>>(qkv, att);

    // 4) out_proj
    split_kernel<<<1024, 256>>>(att, ah, al, NA4);
    split_kernel<<<1024, 256>>>(w_out, wh, wl, NW4);
    gemm_mma_split<<<dim3(E_ / 128, M_TOK / 128), 256, GEMM_SMEM>>>(
        ah, al, wh, wl, b_out, tmp, M_TOK, E_, E_);

    // 5) c_proj
    split_kernel<<<1024, 256>>>(tmp, ah, al, NA4);
    split_kernel<<<1024, 256>>>(w_c, wh, wl, NW4);
    gemm_mma_split<<<dim3(E_ / 128, M_TOK / 128), 256, GEMM_SMEM>>>(
        ah, al, wh, wl, b_c, out, M_TOK, E_, E_);
}

// round 4
// speedup vs baseline: 2.3127x; 1.4623x over previous
#include <cuda_runtime.h>
#include <cuda_bf16.h>
#include <cstdint>
#include <cstddef>

// Problem constants
#define B_  8
#define T_  1024
#define E_  1024
#define H_  16
#define DH_ 64
#define M_TOK (B_ * T_)        // 8192 tokens

// ---------------------------------------------------------------------------
// Scratch (no cudaMalloc allowed -> __device__ globals)
// ---------------------------------------------------------------------------
__device__ __nv_bfloat16 g_qh[(size_t)M_TOK * 3 * E_];     // 48 MB  qkv hi
__device__ __nv_bfloat16 g_ql[(size_t)M_TOK * 3 * E_];     // 48 MB  qkv lo
__device__ __nv_bfloat16 g_ah[(size_t)M_TOK * E_];         // 16 MB  att hi
__device__ __nv_bfloat16 g_al[(size_t)M_TOK * E_];         // 16 MB  att lo
__device__ __nv_bfloat16 g_th[(size_t)M_TOK * E_];         // 16 MB  x / tmp hi
__device__ __nv_bfloat16 g_tl[(size_t)M_TOK * E_];         // 16 MB  x / tmp lo
__device__ __nv_bfloat16 g_wh[(size_t)3 * E_ * E_];        // 6 MB   weight hi
__device__ __nv_bfloat16 g_wl[(size_t)3 * E_ * E_];        // 6 MB   weight lo

// ---------------------------------------------------------------------------
// PTX helpers (portable sm_80+ only; target is base sm_100)
// ---------------------------------------------------------------------------
__device__ __forceinline__ uint32_t smem_to_u32(const void* p) {
    uint32_t a;
    asm("{ .reg .u64 t; cvta.to.shared.u64 t, %1; cvt.u32.u64 %0, t; }"
        : "=r"(a) : "l"(p));
    return a;
}

#define CP_ASYNC16(dst, src) \
    asm volatile("cp.async.cg.shared.global [%0], [%1], 16;" \
                 :: "r"(dst), "l"(src) : "memory")
#define CP_COMMIT() asm volatile("cp.async.commit_group;" ::: "memory")
#define CP_WAIT(n)  asm volatile("cp.async.wait_group %0;" :: "n"(n) : "memory")

#define LDSM_X4(r, addr) \
    asm volatile("ldmatrix.sync.aligned.m8n8.x4.shared.b16 {%0,%1,%2,%3}, [%4];" \
                 : "=r"((r)[0]), "=r"((r)[1]), "=r"((r)[2]), "=r"((r)[3]) \
                 : "r"(addr))
#define LDSM_X2(r, addr) \
    asm volatile("ldmatrix.sync.aligned.m8n8.x2.shared.b16 {%0,%1}, [%2];" \
                 : "=r"((r)[0]), "=r"((r)[1]) : "r"(addr))
#define LDSM_X2T(r, addr) \
    asm volatile("ldmatrix.sync.aligned.m8n8.x2.trans.shared.b16 {%0,%1}, [%2];" \
                 : "=r"((r)[0]), "=r"((r)[1]) : "r"(addr))

#define MMA_BF16(c, a, b) \
    asm volatile("mma.sync.aligned.m16n8k16.row.col.f32.bf16.bf16.f32 " \
                 "{%0,%1,%2,%3}, {%4,%5,%6,%7}, {%8,%9}, {%0,%1,%2,%3};" \
                 : "+f"((c)[0]), "+f"((c)[1]), "+f"((c)[2]), "+f"((c)[3]) \
                 : "r"((a)[0]), "r"((a)[1]), "r"((a)[2]), "r"((a)[3]), \
                   "r"((b)[0]), "r"((b)[1]))

__device__ __forceinline__ uint32_t pack_bf(__nv_bfloat16 a, __nv_bfloat16 b) {
    __nv_bfloat162 t = __halves2bfloat162(a, b);
    return *reinterpret_cast<uint32_t*>(&t);
}

// split 2 floats into hi/lo bf16x2 words; returns hi, writes lo
__device__ __forceinline__ uint32_t pack_hi2(float x, float y, uint32_t& lo) {
    __nv_bfloat16 hx = __float2bfloat16_rn(x), hy = __float2bfloat16_rn(y);
    __nv_bfloat16 lx = __float2bfloat16_rn(x - __bfloat162float(hx));
    __nv_bfloat16 ly = __float2bfloat16_rn(y - __bfloat162float(hy));
    lo = pack_bf(lx, ly);
    return pack_bf(hx, hy);
}

// ---------------------------------------------------------------------------
// fp32 -> (bf16 hi, bf16 lo) split, vectorized
// ---------------------------------------------------------------------------
__global__ void split_kernel(const float* __restrict__ x,
                             __nv_bfloat16* __restrict__ hi,
                             __nv_bfloat16* __restrict__ lo, int n4) {
    int i = blockIdx.x * blockDim.x + threadIdx.x;
    int stride = gridDim.x * blockDim.x;
    for (; i < n4; i += stride) {
        float4 v = ((const float4*)x)[i];
        uint32_t l0, l1;
        uint32_t h0 = pack_hi2(v.x, v.y, l0);
        uint32_t h1 = pack_hi2(v.z, v.w, l1);
        ((uint2*)hi)[i] = make_uint2(h0, h1);
        ((uint2*)lo)[i] = make_uint2(l0, l1);
    }
}

// ---------------------------------------------------------------------------
// mma.sync bf16 split GEMM: C = Ah*Bh^T + Ah*Bl^T + Al*Bh^T + bias
// out_bf16=0 -> Cf fp32;  out_bf16=1 -> (Ch,Cl) hi/lo bf16.
// cols < scale_cols get *0.125 (exact) -- used to fold 1/sqrt(dh) into Q.
// Block 128x128, 8 warps (64x32), KC=32, double-buffered cp.async.
// ---------------------------------------------------------------------------
#define KC 32
#define STAGE_B 32768
#define GEMM_SMEM (2 * STAGE_B)

__global__ __launch_bounds__(256)
void gemm_mma_split(const __nv_bfloat16* __restrict__ Ah,
                    const __nv_bfloat16* __restrict__ Al,
                    const __nv_bfloat16* __restrict__ Bh,
                    const __nv_bfloat16* __restrict__ Bl,
                    const float* __restrict__ bias,
                    float* __restrict__ Cf,
                    __nv_bfloat16* __restrict__ Ch,
                    __nv_bfloat16* __restrict__ Cl,
                    int M, int N, int K, int out_bf16, int scale_cols)
{
    extern __shared__ char smem[];
    const uint32_t sbase = smem_to_u32(smem);
    const int tid  = threadIdx.x;
    const int wid  = tid >> 5;
    const int lane = tid & 31;
    const int warpM = (wid >> 2) * 64;
    const int warpN = (wid & 3) * 32;
    const int rowA = blockIdx.y * 128;
    const int rowB = blockIdx.x * 128;

    float acc[4][4][4];
#pragma unroll
    for (int mt = 0; mt < 4; mt++)
#pragma unroll
        for (int nt = 0; nt < 4; nt++)
#pragma unroll
            for (int r = 0; r < 4; r++) acc[mt][nt][r] = 0.f;

    const int idx0 = tid * 2;
    const int NC = K / KC;

    auto load_stage = [&](int c, int s) {
        const uint32_t sb = sbase + s * STAGE_B;
#pragma unroll
        for (int e = 0; e < 2; e++) {
            int idx  = idx0 + e;
            int row  = idx >> 2;
            int unit = idx & 3;
            uint32_t soff = (uint32_t)(row * 64 + ((unit ^ ((row >> 1) & 3)) << 4));
            size_t goffA = ((size_t)(rowA + row) * K + c * KC + unit * 8) * 2;
            size_t goffB = ((size_t)(rowB + row) * K + c * KC + unit * 8) * 2;
            CP_ASYNC16(sb + soff,         (const char*)Ah + goffA);
            CP_ASYNC16(sb +  8192 + soff, (const char*)Al + goffA);
            CP_ASYNC16(sb + 16384 + soff, (const char*)Bh + goffB);
            CP_ASYNC16(sb + 24576 + soff, (const char*)Bl + goffB);
        }
    };

    load_stage(0, 0);
    CP_COMMIT();

    const int a_row_in = (lane & 7) + ((lane >> 3) & 1) * 8;
    const int a_ksub   = (lane >> 4);
    const int tl       = lane & 15;
    const int b_row_in = tl & 7;
    const int b_ksub   = (tl >> 3) & 1;

    for (int c = 0; c < NC; c++) {
        if (c + 1 < NC) {
            load_stage(c + 1, (c + 1) & 1);
            CP_COMMIT();
            CP_WAIT(1);
        } else {
            CP_WAIT(0);
        }
        __syncthreads();

        const uint32_t sb = sbase + (c & 1) * STAGE_B;

#pragma unroll
        for (int p = 0; p < 3; p++) {
            const uint32_t abase = sb + (p == 2 ? 8192 : 0);
            const uint32_t bbase = sb + 16384 + (p == 1 ? 8192 : 0);
#pragma unroll
            for (int j = 0; j < 2; j++) {
                uint32_t a[4][4];
                uint32_t b[4][2];
                const int aunit = j * 2 + a_ksub;
                const int bunit = j * 2 + b_ksub;
#pragma unroll
                for (int mt = 0; mt < 4; mt++) {
                    int row = warpM + mt * 16 + a_row_in;
                    uint32_t addr = abase + row * 64 +
                                    ((aunit ^ ((row >> 1) & 3)) << 4);
                    LDSM_X4(a[mt], addr);
                }
#pragma unroll
                for (int nt = 0; nt < 4; nt++) {
                    int row = warpN + nt * 8 + b_row_in;
                    uint32_t addr = bbase + row * 64 +
                                    ((bunit ^ ((row >> 1) & 3)) << 4);
                    LDSM_X2(b[nt], addr);
                }
#pragma unroll
                for (int mt = 0; mt < 4; mt++)
#pragma unroll
                    for (int nt = 0; nt < 4; nt++)
                        MMA_BF16(acc[mt][nt], a[mt], b[nt]);
            }
        }
        __syncthreads();
    }

    // epilogue
    const int erow = lane >> 2;
    const int ecol = (lane & 3) * 2;
#pragma unroll
    for (int mt = 0; mt < 4; mt++) {
#pragma unroll
        for (int nt = 0; nt < 4; nt++) {
            int gr = rowA + warpM + mt * 16 + erow;
            int gc = rowB + warpN + nt * 8 + ecol;
            float b0 = __ldg(bias + gc);
            float b1 = __ldg(bias + gc + 1);
            float sc = (gc < scale_cols) ? 0.125f : 1.0f;
            float v00 = (acc[mt][nt][0] + b0) * sc;
            float v01 = (acc[mt][nt][1] + b1) * sc;
            float v10 = (acc[mt][nt][2] + b0) * sc;
            float v11 = (acc[mt][nt][3] + b1) * sc;
            if (out_bf16) {
                uint32_t lo, hi;
                hi = pack_hi2(v00, v01, lo);
                *(uint32_t*)(Ch + (size_t)gr * N + gc) = hi;
                *(uint32_t*)(Cl + (size_t)gr * N + gc) = lo;
                hi = pack_hi2(v10, v11, lo);
                *(uint32_t*)(Ch + (size_t)(gr + 8) * N + gc) = hi;
                *(uint32_t*)(Cl + (size_t)(gr + 8) * N + gc) = lo;
            } else {
                *(float2*)(Cf + (size_t)gr * N + gc)       = make_float2(v00, v01);
                *(float2*)(Cf + (size_t)(gr + 8) * N + gc) = make_float2(v10, v11);
            }
        }
    }
}

// ---------------------------------------------------------------------------
// Flash attention with mma.sync bf16 split arithmetic.
// qkv hi/lo: [B,T,3E] bf16 (Q already scaled by 0.125). out: att hi/lo [B,T,E].
// Block: 128 threads (4 warps), 64 q-rows; K/V in 64-key tiles, cp.async
// double-buffered. grid (16, 128).
// smem: Qh|Ql (16 KB) + 2 stages x (Kh|Kl|Vh|Vl = 32 KB) = 80 KB.
// ---------------------------------------------------------------------------
#define ATTN_SMEM (16384 + 2 * 32768)

__global__ __launch_bounds__(128, 2)
void attn_mma(const __nv_bfloat16* __restrict__ qkvh,
              const __nv_bfloat16* __restrict__ qkvl,
              __nv_bfloat16* __restrict__ oh,
              __nv_bfloat16* __restrict__ ol)
{
    extern __shared__ char smem[];
    const uint32_t sbase = smem_to_u32(smem);
    const int tid  = threadIdx.x;
    const int lane = tid & 31;
    const int warp = tid >> 5;
    const int qt = blockIdx.x;
    const int bh = blockIdx.y;
    const int b = bh >> 4;
    const int h = bh & 15;

    const uint32_t sQh = sbase;
    const uint32_t sQl = sbase + 8192;

    const size_t tok0 = (size_t)b * T_;
    const size_t rs = 3 * E_;           // qkv token stride (elements)

    // ---- load Q tile (hi/lo) ----
    {
        const __nv_bfloat16* qb_h = qkvh + (tok0 + qt * 64) * rs + h * DH_;
        const __nv_bfloat16* qb_l = qkvl + (tok0 + qt * 64) * rs + h * DH_;
#pragma unroll
        for (int it = 0; it < 4; it++) {
            int idx = tid + it * 128;
            int row = idx >> 3, unit = idx & 7;
            uint32_t off = (uint32_t)(row * 128 + ((unit ^ (row & 7)) << 4));
            CP_ASYNC16(sQh + off, (const char*)(qb_h + (size_t)row * rs) + unit * 16);
            CP_ASYNC16(sQl + off, (const char*)(qb_l + (size_t)row * rs) + unit * 16);
        }
    }

    auto load_kv = [&](int kt, int s) {
        uint32_t sb = sbase + 16384 + s * 32768;
        const __nv_bfloat16* kh = qkvh + (tok0 + kt * 64) * rs + E_ + h * DH_;
        const __nv_bfloat16* kl = qkvl + (tok0 + kt * 64) * rs + E_ + h * DH_;
#pragma unroll
        for (int it = 0; it < 4; it++) {
            int idx = tid + it * 128;
            int row = idx >> 3, unit = idx & 7;
            uint32_t off = (uint32_t)(row * 128 + ((unit ^ (row & 7)) << 4));
            size_t g = (size_t)row * rs;
            CP_ASYNC16(sb +         off, (const char*)(kh + g) + unit * 16);
            CP_ASYNC16(sb +  8192 + off, (const char*)(kl + g) + unit * 16);
            CP_ASYNC16(sb + 16384 + off, (const char*)(kh + E_ + g) + unit * 16);
            CP_ASYNC16(sb + 24576 + off, (const char*)(kl + E_ + g) + unit * 16);
        }
    };

    load_kv(0, 0);
    CP_COMMIT();

    const int tl   = lane & 15;
    const int arow = warp * 16 + tl;      // Q row for ldsm x4
    const int aun  = lane >> 4;           // 0/1 k-unit select
    const int brw  = tl & 7;              // K/V ldsm x2 row base
    const int bks  = (tl >> 3) & 1;       // k-half select

    float O[8][4];
#pragma unroll
    for (int t = 0; t < 8; t++)
#pragma unroll
        for (int r = 0; r < 4; r++) O[t][r] = 0.f;
    float m0 = -1e30f, m1 = -1e30f, l0 = 0.f, l1 = 0.f;

    for (int kt = 0; kt <= qt; kt++) {
        CP_WAIT(0);
        __syncthreads();
        if (kt < qt) { load_kv(kt + 1, (kt + 1) & 1); CP_COMMIT(); }

        const uint32_t sb  = sbase + 16384 + (kt & 1) * 32768;
        const uint32_t sKh = sb, sKl = sb + 8192;
        const uint32_t sVh = sb + 16384, sVl = sb + 24576;

        // ---- S = Q K^T (3-term split, fp32 accum) ----
        float S[8][4];
#pragma unroll
        for (int t = 0; t < 8; t++)
#pragma unroll
            for (int r = 0; r < 4; r++) S[t][r] = 0.f;

#pragma unroll
        for (int j = 0; j < 4; j++) {
            uint32_t aH[4], aL[4];
            int au = j * 2 + aun;
            uint32_t aoff = (uint32_t)(arow * 128 + ((au ^ (arow & 7)) << 4));
            LDSM_X4(aH, sQh + aoff);
            LDSM_X4(aL, sQl + aoff);
#pragma unroll
            for (int t = 0; t < 8; t++) {
                int r = t * 8 + brw;
                int u = j * 2 + bks;
                uint32_t boff = (uint32_t)(r * 128 + ((u ^ (r & 7)) << 4));
                uint32_t bH[2], bL[2];
                LDSM_X2(bH, sKh + boff);
                LDSM_X2(bL, sKl + boff);
                MMA_BF16(S[t], aH, bH);
                MMA_BF16(S[t], aH, bL);
                MMA_BF16(S[t], aL, bH);
            }
        }

        // ---- causal mask on diagonal tile ----
        if (kt == qt) {
            int r0 = warp * 16 + (lane >> 2);
#pragma unroll
            for (int t = 0; t < 8; t++) {
                int c = t * 8 + (lane & 3) * 2;
                if (c     > r0)     S[t][0] = -1e30f;
                if (c + 1 > r0)     S[t][1] = -1e30f;
                if (c     > r0 + 8) S[t][2] = -1e30f;
                if (c + 1 > r0 + 8) S[t][3] = -1e30f;
            }
        }

        // ---- online softmax ----
        float rm0 = -1e30f, rm1 = -1e30f;
#pragma unroll
        for (int t = 0; t < 8; t++) {
            rm0 = fmaxf(rm0, fmaxf(S[t][0], S[t][1]));
            rm1 = fmaxf(rm1, fmaxf(S[t][2], S[t][3]));
        }
        rm0 = fmaxf(rm0, __shfl_xor_sync(0xffffffffu, rm0, 1));
        rm0 = fmaxf(rm0, __shfl_xor_sync(0xffffffffu, rm0, 2));
        rm1 = fmaxf(rm1, __shfl_xor_sync(0xffffffffu, rm1, 1));
        rm1 = fmaxf(rm1, __shfl_xor_sync(0xffffffffu, rm1, 2));
        float mn0 = fmaxf(m0, rm0), mn1 = fmaxf(m1, rm1);
        float al0 = __expf(m0 - mn0), al1 = __expf(m1 - mn1);
        m0 = mn0; m1 = mn1;

        float ls0 = 0.f, ls1 = 0.f;
#pragma unroll
        for (int t = 0; t < 8; t++) {
            S[t][0] = __expf(S[t][0] - mn0); ls0 += S[t][0];
            S[t][1] = __expf(S[t][1] - mn0); ls0 += S[t][1];
            S[t][2] = __expf(S[t][2] - mn1); ls1 += S[t][2];
            S[t][3] = __expf(S[t][3] - mn1); ls1 += S[t][3];
        }
        l0 = l0 * al0 + ls0;
        l1 = l1 * al1 + ls1;
#pragma unroll
        for (int t = 0; t < 8; t++) {
            O[t][0] *= al0; O[t][1] *= al0;
            O[t][2] *= al1; O[t][3] *= al1;
        }

        // ---- pack P to hi/lo A-fragments ----
        uint32_t pH[4][4], pL[4][4];
#pragma unroll
        for (int j = 0; j < 4; j++) {
            pH[j][0] = pack_hi2(S[2*j][0],   S[2*j][1],   pL[j][0]);
            pH[j][1] = pack_hi2(S[2*j][2],   S[2*j][3],   pL[j][1]);
            pH[j][2] = pack_hi2(S[2*j+1][0], S[2*j+1][1], pL[j][2]);
            pH[j][3] = pack_hi2(S[2*j+1][2], S[2*j+1][3], pL[j][3]);
        }

        // ---- O += P V (3-term split; V via ldmatrix.trans) ----
#pragma unroll
        for (int j = 0; j < 4; j++) {
            int vr = j * 16 + brw + bks * 8;
#pragma unroll
            for (int t = 0; t < 8; t++) {
                uint32_t voff = (uint32_t)(vr * 128 + ((t ^ (vr & 7)) << 4));
                uint32_t vH[2], vL[2];
                LDSM_X2T(vH, sVh + voff);
                LDSM_X2T(vL, sVl + voff);
                MMA_BF16(O[t], pH[j], vH);
                MMA_BF16(O[t], pL[j], vH);
                MMA_BF16(O[t], pH[j], vL);
            }
        }
    }

    // ---- epilogue: normalize, split to hi/lo bf16, store ----
    l0 += __shfl_xor_sync(0xffffffffu, l0, 1);
    l0 += __shfl_xor_sync(0xffffffffu, l0, 2);
    l1 += __shfl_xor_sync(0xffffffffu, l1, 1);
    l1 += __shfl_xor_sync(0xffffffffu, l1, 2);
    float inv0 = 1.f / l0, inv1 = 1.f / l1;

    int r0 = qt * 64 + warp * 16 + (lane >> 2);
    size_t grow0 = (tok0 + r0) * E_ + h * DH_;
    size_t grow1 = grow0 + (size_t)8 * E_;
#pragma unroll
    for (int t = 0; t < 8; t++) {
        int c = t * 8 + (lane & 3) * 2;
        uint32_t lo, hi;
        hi = pack_hi2(O[t][0] * inv0, O[t][1] * inv0, lo);
        *(uint32_t*)(oh + grow0 + c) = hi;
        *(uint32_t*)(ol + grow0 + c) = lo;
        hi = pack_hi2(O[t][2] * inv1, O[t][3] * inv1, lo);
        *(uint32_t*)(oh + grow1 + c) = hi;
        *(uint32_t*)(ol + grow1 + c) = lo;
    }
}

// ---------------------------------------------------------------------------
// kernel_launch
// inputs: x, in_proj_w, in_proj_b, out_proj_w, out_proj_b, c_proj_w, c_proj_b
// ---------------------------------------------------------------------------
extern "C" void kernel_launch(void* const* d_in, const int* in_sizes, int n_in,
                              void* d_out, int out_size)
{
    const float* x     = (const float*)d_in[0];
    const float* w_in  = (const float*)d_in[1];
    const float* b_in  = (const float*)d_in[2];
    const float* w_out = (const float*)d_in[3];
    const float* b_out = (const float*)d_in[4];
    const float* w_c   = (const float*)d_in[5];
    const float* b_c   = (const float*)d_in[6];
    float* out = (float*)d_out;

    __nv_bfloat16 *qh, *ql, *ah, *al, *th, *tlp, *wh, *wl;
    cudaGetSymbolAddress((void**)&qh, g_qh);
    cudaGetSymbolAddress((void**)&ql, g_ql);
    cudaGetSymbolAddress((void**)&ah, g_ah);
    cudaGetSymbolAddress((void**)&al, g_al);
    cudaGetSymbolAddress((void**)&th, g_th);
    cudaGetSymbolAddress((void**)&tlp, g_tl);
    cudaGetSymbolAddress((void**)&wh, g_wh);
    cudaGetSymbolAddress((void**)&wl, g_wl);

    cudaFuncSetAttribute(gemm_mma_split,
                         cudaFuncAttributeMaxDynamicSharedMemorySize, GEMM_SMEM);
    cudaFuncSetAttribute(attn_mma,
                         cudaFuncAttributeMaxDynamicSharedMemorySize, ATTN_SMEM);

    const int NA4   = M_TOK * E_ / 4;
    const int NWIN4 = 3 * E_ * E_ / 4;
    const int NW4   = E_ * E_ / 4;

    // 1) split x and in_proj_w
    split_kernel<<<1024, 256>>>(x, th, tlp, NA4);
    split_kernel<<<1024, 256>>>(w_in, wh, wl, NWIN4);

    // 2) QKV GEMM -> bf16 hi/lo qkv, Q cols scaled by 1/8
    gemm_mma_split<<<dim3(3 * E_ / 128, M_TOK / 128), 256, GEMM_SMEM>>>(
        th, tlp, wh, wl, b_in, nullptr, qh, ql, M_TOK, 3 * E_, E_, 1, E_);

    // 3) flash attention (tensor cores) -> att hi/lo
    attn_mma<<<dim3(T_ / 64, B_ * H_), 128, ATTN_SMEM>>>(qh, ql, ah, al);

    // 4) out_proj -> tmp hi/lo
    split_kernel<<<1024, 256>>>(w_out, wh, wl, NW4);
    gemm_mma_split<<<dim3(E_ / 128, M_TOK / 128), 256, GEMM_SMEM>>>(
        ah, al, wh, wl, b_out, nullptr, th, tlp, M_TOK, E_, E_, 1, 0);

    // 5) c_proj -> fp32 out
    split_kernel<<<1024, 256>>>(w_c, wh, wl, NW4);
    gemm_mma_split<<<dim3(E_ / 128, M_TOK / 128), 256, GEMM_SMEM>>>(
        th, tlp, wh, wl, b_c, out, nullptr, nullptr, M_TOK, E_, E_, 0, 0);
}

// round 5
// speedup vs baseline: 3.0194x; 1.3056x over previous
#include <cuda_runtime.h>
#include <cuda_bf16.h>
#include <cstdint>
#include <cstddef>

// Problem constants
#define B_  8
#define T_  1024
#define E_  1024
#define H_  16
#define DH_ 64
#define M_TOK (B_ * T_)        // 8192 tokens
#define E2_ ((size_t)E_ * E_)

// ---------------------------------------------------------------------------
// Scratch (no cudaMalloc allowed -> __device__ globals)
// ---------------------------------------------------------------------------
__device__ __nv_bfloat16 g_qh[(size_t)M_TOK * 3 * E_];     // 48 MB  qkv hi
__device__ __nv_bfloat16 g_ql[(size_t)M_TOK * 3 * E_];     // 48 MB  qkv lo
__device__ __nv_bfloat16 g_ah[(size_t)M_TOK * E_];         // 16 MB  att hi
__device__ __nv_bfloat16 g_al[(size_t)M_TOK * E_];         // 16 MB  att lo
__device__ __nv_bfloat16 g_th[(size_t)M_TOK * E_];         // 16 MB  x hi
__device__ __nv_bfloat16 g_tl[(size_t)M_TOK * E_];         // 16 MB  x lo
__device__ __nv_bfloat16 g_wh[(size_t)3 * E_ * E_];        // 6 MB   weight hi
__device__ __nv_bfloat16 g_wl[(size_t)3 * E_ * E_];        // 6 MB   weight lo
__device__ float g_biasf[E_];                              // fused bias
__device__ float g_zero[E_];                               // zeros (.bss)

// ---------------------------------------------------------------------------
// PTX helpers (portable sm_80+ only; target is base sm_100)
// ---------------------------------------------------------------------------
__device__ __forceinline__ uint32_t smem_to_u32(const void* p) {
    uint32_t a;
    asm("{ .reg .u64 t; cvta.to.shared.u64 t, %1; cvt.u32.u64 %0, t; }"
        : "=r"(a) : "l"(p));
    return a;
}

#define CP_ASYNC16(dst, src) \
    asm volatile("cp.async.cg.shared.global [%0], [%1], 16;" \
                 :: "r"(dst), "l"(src) : "memory")
#define CP_COMMIT() asm volatile("cp.async.commit_group;" ::: "memory")
#define CP_WAIT(n)  asm volatile("cp.async.wait_group %0;" :: "n"(n) : "memory")

#define LDSM_X4(r, addr) \
    asm volatile("ldmatrix.sync.aligned.m8n8.x4.shared.b16 {%0,%1,%2,%3}, [%4];" \
                 : "=r"((r)[0]), "=r"((r)[1]), "=r"((r)[2]), "=r"((r)[3]) \
                 : "r"(addr))
#define LDSM_X2(r, addr) \
    asm volatile("ldmatrix.sync.aligned.m8n8.x2.shared.b16 {%0,%1}, [%2];" \
                 : "=r"((r)[0]), "=r"((r)[1]) : "r"(addr))
#define LDSM_X2T(r, addr) \
    asm volatile("ldmatrix.sync.aligned.m8n8.x2.trans.shared.b16 {%0,%1}, [%2];" \
                 : "=r"((r)[0]), "=r"((r)[1]) : "r"(addr))

#define MMA_BF16(c, a, b) \
    asm volatile("mma.sync.aligned.m16n8k16.row.col.f32.bf16.bf16.f32 " \
                 "{%0,%1,%2,%3}, {%4,%5,%6,%7}, {%8,%9}, {%0,%1,%2,%3};" \
                 : "+f"((c)[0]), "+f"((c)[1]), "+f"((c)[2]), "+f"((c)[3]) \
                 : "r"((a)[0]), "r"((a)[1]), "r"((a)[2]), "r"((a)[3]), \
                   "r"((b)[0]), "r"((b)[1]))

__device__ __forceinline__ uint32_t pack_bf(__nv_bfloat16 a, __nv_bfloat16 b) {
    __nv_bfloat162 t = __halves2bfloat162(a, b);
    return *reinterpret_cast<uint32_t*>(&t);
}

// split 2 floats into hi/lo bf16x2 words; returns hi, writes lo
__device__ __forceinline__ uint32_t pack_hi2(float x, float y, uint32_t& lo) {
    __nv_bfloat16 hx = __float2bfloat16_rn(x), hy = __float2bfloat16_rn(y);
    __nv_bfloat16 lx = __float2bfloat16_rn(x - __bfloat162float(hx));
    __nv_bfloat16 ly = __float2bfloat16_rn(y - __bfloat162float(hy));
    lo = pack_bf(lx, ly);
    return pack_bf(hx, hy);
}

// ---------------------------------------------------------------------------
// fp32 -> (bf16 hi, bf16 lo) split, vectorized
// ---------------------------------------------------------------------------
__global__ void split_kernel(const float* __restrict__ x,
                             __nv_bfloat16* __restrict__ hi,
                             __nv_bfloat16* __restrict__ lo, int n4) {
    int i = blockIdx.x * blockDim.x + threadIdx.x;
    int stride = gridDim.x * blockDim.x;
    for (; i < n4; i += stride) {
        float4 v = ((const float4*)x)[i];
        uint32_t l0, l1;
        uint32_t h0 = pack_hi2(v.x, v.y, l0);
        uint32_t h1 = pack_hi2(v.z, v.w, l1);
        ((uint2*)hi)[i] = make_uint2(h0, h1);
        ((uint2*)lo)[i] = make_uint2(l0, l1);
    }
}

// ---------------------------------------------------------------------------
// fp32 [E,E] -> transposed hi/lo bf16 [E,E] (out[i][j] = in[j][i])
// ---------------------------------------------------------------------------
__global__ void split_transpose_kernel(const float* __restrict__ x,
                                       __nv_bfloat16* __restrict__ hi,
                                       __nv_bfloat16* __restrict__ lo) {
    __shared__ float tile[32][33];
    const int bx = blockIdx.x * 32, by = blockIdx.y * 32;
    const int tx = threadIdx.x, ty = threadIdx.y;     // 32 x 8
#pragma unroll
    for (int u = 0; u < 4; u++)
        tile[ty + u * 8][tx] = x[(size_t)(by + ty + u * 8) * E_ + bx + tx];
    __syncthreads();
#pragma unroll
    for (int u = 0; u < 4; u++) {
        int r = ty + u * 8;
        float v = tile[tx][r];
        __nv_bfloat16 h = __float2bfloat16_rn(v);
        __nv_bfloat16 l = __float2bfloat16_rn(v - __bfloat162float(h));
        hi[(size_t)(bx + r) * E_ + by + tx] = h;
        lo[(size_t)(bx + r) * E_ + by + tx] = l;
    }
}

// ---------------------------------------------------------------------------
// fused bias: bf[n] = bc[n] + sum_k bo[k] * Wc[n,k]     (grid E_, block 256)
// ---------------------------------------------------------------------------
__global__ void bias_fuse_kernel(const float* __restrict__ wc,
                                 const float* __restrict__ bo,
                                 const float* __restrict__ bc,
                                 float* __restrict__ bf) {
    __shared__ float red[8];
    const int n = blockIdx.x, tid = threadIdx.x;
    float s = 0.f;
    for (int k = tid; k < E_; k += 256)
        s += wc[(size_t)n * E_ + k] * bo[k];
#pragma unroll
    for (int o = 16; o > 0; o >>= 1) s += __shfl_xor_sync(0xffffffffu, s, o);
    if ((tid & 31) == 0) red[tid >> 5] = s;
    __syncthreads();
    if (tid == 0) {
        float t = 0.f;
#pragma unroll
        for (int w = 0; w < 8; w++) t += red[w];
        bf[n] = t + bc[n];
    }
}

// ---------------------------------------------------------------------------
// mma.sync bf16 split GEMM: C = Ah*Bh^T + Ah*Bl^T + Al*Bh^T + bias
// out_bf16=0 -> Cf fp32;  out_bf16=1 -> (Ch,Cl) hi/lo bf16.
// cols < scale_cols get *0.125 (exact) -- folds 1/sqrt(dh) into Q.
// Block 128x128, 8 warps (64x32), KC=32, double-buffered cp.async.
// Inner loop: operands loaded ONCE per k16 step, 3 mma terms from registers.
// ---------------------------------------------------------------------------
#define KC 32
#define STAGE_B 32768
#define GEMM_SMEM (2 * STAGE_B)

__global__ __launch_bounds__(256)
void gemm_mma_split(const __nv_bfloat16* __restrict__ Ah,
                    const __nv_bfloat16* __restrict__ Al,
                    const __nv_bfloat16* __restrict__ Bh,
                    const __nv_bfloat16* __restrict__ Bl,
                    const float* __restrict__ bias,
                    float* __restrict__ Cf,
                    __nv_bfloat16* __restrict__ Ch,
                    __nv_bfloat16* __restrict__ Cl,
                    int M, int N, int K, int out_bf16, int scale_cols)
{
    extern __shared__ char smem[];
    const uint32_t sbase = smem_to_u32(smem);
    const int tid  = threadIdx.x;
    const int wid  = tid >> 5;
    const int lane = tid & 31;
    const int warpM = (wid >> 2) * 64;
    const int warpN = (wid & 3) * 32;
    const int rowA = blockIdx.y * 128;
    const int rowB = blockIdx.x * 128;

    float acc[4][4][4];
#pragma unroll
    for (int mt = 0; mt < 4; mt++)
#pragma unroll
        for (int nt = 0; nt < 4; nt++)
#pragma unroll
            for (int r = 0; r < 4; r++) acc[mt][nt][r] = 0.f;

    const int idx0 = tid * 2;
    const int NC = K / KC;

    auto load_stage = [&](int c, int s) {
        const uint32_t sb = sbase + s * STAGE_B;
#pragma unroll
        for (int e = 0; e < 2; e++) {
            int idx  = idx0 + e;
            int row  = idx >> 2;
            int unit = idx & 3;
            uint32_t soff = (uint32_t)(row * 64 + ((unit ^ ((row >> 1) & 3)) << 4));
            size_t goffA = ((size_t)(rowA + row) * K + c * KC + unit * 8) * 2;
            size_t goffB = ((size_t)(rowB + row) * K + c * KC + unit * 8) * 2;
            CP_ASYNC16(sb + soff,         (const char*)Ah + goffA);
            CP_ASYNC16(sb +  8192 + soff, (const char*)Al + goffA);
            CP_ASYNC16(sb + 16384 + soff, (const char*)Bh + goffB);
            CP_ASYNC16(sb + 24576 + soff, (const char*)Bl + goffB);
        }
    };

    load_stage(0, 0);
    CP_COMMIT();

    const int a_row_in = (lane & 7) + ((lane >> 3) & 1) * 8;
    const int a_ksub   = (lane >> 4);
    const int tl       = lane & 15;
    const int b_row_in = tl & 7;
    const int b_ksub   = (tl >> 3) & 1;

    for (int c = 0; c < NC; c++) {
        if (c + 1 < NC) {
            load_stage(c + 1, (c + 1) & 1);
            CP_COMMIT();
            CP_WAIT(1);
        } else {
            CP_WAIT(0);
        }
        __syncthreads();

        const uint32_t sb = sbase + (c & 1) * STAGE_B;

#pragma unroll
        for (int j = 0; j < 2; j++) {
            uint32_t aH[4][4], aL[4][4];
            uint32_t bH[4][2], bL[4][2];
            const int aunit = j * 2 + a_ksub;
            const int bunit = j * 2 + b_ksub;
#pragma unroll
            for (int mt = 0; mt < 4; mt++) {
                int row = warpM + mt * 16 + a_row_in;
                uint32_t xo = ((aunit ^ ((row >> 1) & 3)) << 4);
                LDSM_X4(aH[mt], sb + row * 64 + xo);
                LDSM_X4(aL[mt], sb + 8192 + row * 64 + xo);
            }
#pragma unroll
            for (int nt = 0; nt < 4; nt++) {
                int row = warpN + nt * 8 + b_row_in;
                uint32_t xo = ((bunit ^ ((row >> 1) & 3)) << 4);
                LDSM_X2(bH[nt], sb + 16384 + row * 64 + xo);
                LDSM_X2(bL[nt], sb + 24576 + row * 64 + xo);
            }
#pragma unroll
            for (int mt = 0; mt < 4; mt++)
#pragma unroll
                for (int nt = 0; nt < 4; nt++) {
                    MMA_BF16(acc[mt][nt], aH[mt], bH[nt]);
                    MMA_BF16(acc[mt][nt], aH[mt], bL[nt]);
                    MMA_BF16(acc[mt][nt], aL[mt], bH[nt]);
                }
        }
        __syncthreads();
    }

    // epilogue
    const int erow = lane >> 2;
    const int ecol = (lane & 3) * 2;
#pragma unroll
    for (int mt = 0; mt < 4; mt++) {
#pragma unroll
        for (int nt = 0; nt < 4; nt++) {
            int gr = rowA + warpM + mt * 16 + erow;
            int gc = rowB + warpN + nt * 8 + ecol;
            float b0 = __ldg(bias + gc);
            float b1 = __ldg(bias + gc + 1);
            float sc = (gc < scale_cols) ? 0.125f : 1.0f;
            float v00 = (acc[mt][nt][0] + b0) * sc;
            float v01 = (acc[mt][nt][1] + b1) * sc;
            float v10 = (acc[mt][nt][2] + b0) * sc;
            float v11 = (acc[mt][nt][3] + b1) * sc;
            if (out_bf16) {
                uint32_t lo, hi;
                hi = pack_hi2(v00, v01, lo);
                *(uint32_t*)(Ch + (size_t)gr * N + gc) = hi;
                *(uint32_t*)(Cl + (size_t)gr * N + gc) = lo;
                hi = pack_hi2(v10, v11, lo);
                *(uint32_t*)(Ch + (size_t)(gr + 8) * N + gc) = hi;
                *(uint32_t*)(Cl + (size_t)(gr + 8) * N + gc) = lo;
            } else {
                *(float2*)(Cf + (size_t)gr * N + gc)       = make_float2(v00, v01);
                *(float2*)(Cf + (size_t)(gr + 8) * N + gc) = make_float2(v10, v11);
            }
        }
    }
}

// ---------------------------------------------------------------------------
// Flash attention with mma.sync bf16 split arithmetic (unchanged, 181us).
// ---------------------------------------------------------------------------
#define ATTN_SMEM (16384 + 2 * 32768)

__global__ __launch_bounds__(128, 2)
void attn_mma(const __nv_bfloat16* __restrict__ qkvh,
              const __nv_bfloat16* __restrict__ qkvl,
              __nv_bfloat16* __restrict__ oh,
              __nv_bfloat16* __restrict__ ol)
{
    extern __shared__ char smem[];
    const uint32_t sbase = smem_to_u32(smem);
    const int tid  = threadIdx.x;
    const int lane = tid & 31;
    const int warp = tid >> 5;
    const int qt = blockIdx.x;
    const int bh = blockIdx.y;
    const int b = bh >> 4;
    const int h = bh & 15;

    const uint32_t sQh = sbase;
    const uint32_t sQl = sbase + 8192;

    const size_t tok0 = (size_t)b * T_;
    const size_t rs = 3 * E_;

    {
        const __nv_bfloat16* qb_h = qkvh + (tok0 + qt * 64) * rs + h * DH_;
        const __nv_bfloat16* qb_l = qkvl + (tok0 + qt * 64) * rs + h * DH_;
#pragma unroll
        for (int it = 0; it < 4; it++) {
            int idx = tid + it * 128;
            int row = idx >> 3, unit = idx & 7;
            uint32_t off = (uint32_t)(row * 128 + ((unit ^ (row & 7)) << 4));
            CP_ASYNC16(sQh + off, (const char*)(qb_h + (size_t)row * rs) + unit * 16);
            CP_ASYNC16(sQl + off, (const char*)(qb_l + (size_t)row * rs) + unit * 16);
        }
    }

    auto load_kv = [&](int kt, int s) {
        uint32_t sb = sbase + 16384 + s * 32768;
        const __nv_bfloat16* kh = qkvh + (tok0 + kt * 64) * rs + E_ + h * DH_;
        const __nv_bfloat16* kl = qkvl + (tok0 + kt * 64) * rs + E_ + h * DH_;
#pragma unroll
        for (int it = 0; it < 4; it++) {
            int idx = tid + it * 128;
            int row = idx >> 3, unit = idx & 7;
            uint32_t off = (uint32_t)(row * 128 + ((unit ^ (row & 7)) << 4));
            size_t g = (size_t)row * rs;
            CP_ASYNC16(sb +         off, (const char*)(kh + g) + unit * 16);
            CP_ASYNC16(sb +  8192 + off, (const char*)(kl + g) + unit * 16);
            CP_ASYNC16(sb + 16384 + off, (const char*)(kh + E_ + g) + unit * 16);
            CP_ASYNC16(sb + 24576 + off, (const char*)(kl + E_ + g) + unit * 16);
        }
    };

    load_kv(0, 0);
    CP_COMMIT();

    const int tl   = lane & 15;
    const int arow = warp * 16 + tl;
    const int aun  = lane >> 4;
    const int brw  = tl & 7;
    const int bks  = (tl >> 3) & 1;

    float O[8][4];
#pragma unroll
    for (int t = 0; t < 8; t++)
#pragma unroll
        for (int r = 0; r < 4; r++) O[t][r] = 0.f;
    float m0 = -1e30f, m1 = -1e30f, l0 = 0.f, l1 = 0.f;

    for (int kt = 0; kt <= qt; kt++) {
        CP_WAIT(0);
        __syncthreads();
        if (kt < qt) { load_kv(kt + 1, (kt + 1) & 1); CP_COMMIT(); }

        const uint32_t sb  = sbase + 16384 + (kt & 1) * 32768;
        const uint32_t sKh = sb, sKl = sb + 8192;
        const uint32_t sVh = sb + 16384, sVl = sb + 24576;

        float S[8][4];
#pragma unroll
        for (int t = 0; t < 8; t++)
#pragma unroll
            for (int r = 0; r < 4; r++) S[t][r] = 0.f;

#pragma unroll
        for (int j = 0; j < 4; j++) {
            uint32_t aH[4], aL[4];
            int au = j * 2 + aun;
            uint32_t aoff = (uint32_t)(arow * 128 + ((au ^ (arow & 7)) << 4));
            LDSM_X4(aH, sQh + aoff);
            LDSM_X4(aL, sQl + aoff);
#pragma unroll
            for (int t = 0; t < 8; t++) {
                int r = t * 8 + brw;
                int u = j * 2 + bks;
                uint32_t boff = (uint32_t)(r * 128 + ((u ^ (r & 7)) << 4));
                uint32_t bH[2], bL[2];
                LDSM_X2(bH, sKh + boff);
                LDSM_X2(bL, sKl + boff);
                MMA_BF16(S[t], aH, bH);
                MMA_BF16(S[t], aH, bL);
                MMA_BF16(S[t], aL, bH);
            }
        }

        if (kt == qt) {
            int r0 = warp * 16 + (lane >> 2);
#pragma unroll
            for (int t = 0; t < 8; t++) {
                int c = t * 8 + (lane & 3) * 2;
                if (c     > r0)     S[t][0] = -1e30f;
                if (c + 1 > r0)     S[t][1] = -1e30f;
                if (c     > r0 + 8) S[t][2] = -1e30f;
                if (c + 1 > r0 + 8) S[t][3] = -1e30f;
            }
        }

        float rm0 = -1e30f, rm1 = -1e30f;
#pragma unroll
        for (int t = 0; t < 8; t++) {
            rm0 = fmaxf(rm0, fmaxf(S[t][0], S[t][1]));
            rm1 = fmaxf(rm1, fmaxf(S[t][2], S[t][3]));
        }
        rm0 = fmaxf(rm0, __shfl_xor_sync(0xffffffffu, rm0, 1));
        rm0 = fmaxf(rm0, __shfl_xor_sync(0xffffffffu, rm0, 2));
        rm1 = fmaxf(rm1, __shfl_xor_sync(0xffffffffu, rm1, 1));
        rm1 = fmaxf(rm1, __shfl_xor_sync(0xffffffffu, rm1, 2));
        float mn0 = fmaxf(m0, rm0), mn1 = fmaxf(m1, rm1);
        float al0 = __expf(m0 - mn0), al1 = __expf(m1 - mn1);
        m0 = mn0; m1 = mn1;

        float ls0 = 0.f, ls1 = 0.f;
#pragma unroll
        for (int t = 0; t < 8; t++) {
            S[t][0] = __expf(S[t][0] - mn0); ls0 += S[t][0];
            S[t][1] = __expf(S[t][1] - mn0); ls0 += S[t][1];
            S[t][2] = __expf(S[t][2] - mn1); ls1 += S[t][2];
            S[t][3] = __expf(S[t][3] - mn1); ls1 += S[t][3];
        }
        l0 = l0 * al0 + ls0;
        l1 = l1 * al1 + ls1;
#pragma unroll
        for (int t = 0; t < 8; t++) {
            O[t][0] *= al0; O[t][1] *= al0;
            O[t][2] *= al1; O[t][3] *= al1;
        }

        uint32_t pH[4][4], pL[4][4];
#pragma unroll
        for (int j = 0; j < 4; j++) {
            pH[j][0] = pack_hi2(S[2*j][0],   S[2*j][1],   pL[j][0]);
            pH[j][1] = pack_hi2(S[2*j][2],   S[2*j][3],   pL[j][1]);
            pH[j][2] = pack_hi2(S[2*j+1][0], S[2*j+1][1], pL[j][2]);
            pH[j][3] = pack_hi2(S[2*j+1][2], S[2*j+1][3], pL[j][3]);
        }

#pragma unroll
        for (int j = 0; j < 4; j++) {
            int vr = j * 16 + brw + bks * 8;
#pragma unroll
            for (int t = 0; t < 8; t++) {
                uint32_t voff = (uint32_t)(vr * 128 + ((t ^ (vr & 7)) << 4));
                uint32_t vH[2], vL[2];
                LDSM_X2T(vH, sVh + voff);
                LDSM_X2T(vL, sVl + voff);
                MMA_BF16(O[t], pH[j], vH);
                MMA_BF16(O[t], pL[j], vH);
                MMA_BF16(O[t], pH[j], vL);
            }
        }
    }

    l0 += __shfl_xor_sync(0xffffffffu, l0, 1);
    l0 += __shfl_xor_sync(0xffffffffu, l0, 2);
    l1 += __shfl_xor_sync(0xffffffffu, l1, 1);
    l1 += __shfl_xor_sync(0xffffffffu, l1, 2);
    float inv0 = 1.f / l0, inv1 = 1.f / l1;

    int r0 = qt * 64 + warp * 16 + (lane >> 2);
    size_t grow0 = (tok0 + r0) * E_ + h * DH_;
    size_t grow1 = grow0 + (size_t)8 * E_;
#pragma unroll
    for (int t = 0; t < 8; t++) {
        int c = t * 8 + (lane & 3) * 2;
        uint32_t lo, hi;
        hi = pack_hi2(O[t][0] * inv0, O[t][1] * inv0, lo);
        *(uint32_t*)(oh + grow0 + c) = hi;
        *(uint32_t*)(ol + grow0 + c) = lo;
        hi = pack_hi2(O[t][2] * inv1, O[t][3] * inv1, lo);
        *(uint32_t*)(oh + grow1 + c) = hi;
        *(uint32_t*)(ol + grow1 + c) = lo;
    }
}

// ---------------------------------------------------------------------------
// kernel_launch
// inputs: x, in_proj_w, in_proj_b, out_proj_w, out_proj_b, c_proj_w, c_proj_b
// ---------------------------------------------------------------------------
extern "C" void kernel_launch(void* const* d_in, const int* in_sizes, int n_in,
                              void* d_out, int out_size)
{
    const float* x     = (const float*)d_in[0];
    const float* w_in  = (const float*)d_in[1];
    const float* b_in  = (const float*)d_in[2];
    const float* w_out = (const float*)d_in[3];
    const float* b_out = (const float*)d_in[4];
    const float* w_c   = (const float*)d_in[5];
    const float* b_c   = (const float*)d_in[6];
    float* out = (float*)d_out;

    __nv_bfloat16 *qh, *ql, *ah, *al, *th, *tlp, *wh, *wl;
    float *biasf, *zerov;
    cudaGetSymbolAddress((void**)&qh, g_qh);
    cudaGetSymbolAddress((void**)&ql, g_ql);
    cudaGetSymbolAddress((void**)&ah, g_ah);
    cudaGetSymbolAddress((void**)&al, g_al);
    cudaGetSymbolAddress((void**)&th, g_th);
    cudaGetSymbolAddress((void**)&tlp, g_tl);
    cudaGetSymbolAddress((void**)&wh, g_wh);
    cudaGetSymbolAddress((void**)&wl, g_wl);
    cudaGetSymbolAddress((void**)&biasf, g_biasf);
    cudaGetSymbolAddress((void**)&zerov, g_zero);

    cudaFuncSetAttribute(gemm_mma_split,
                         cudaFuncAttributeMaxDynamicSharedMemorySize, GEMM_SMEM);
    cudaFuncSetAttribute(attn_mma,
                         cudaFuncAttributeMaxDynamicSharedMemorySize, ATTN_SMEM);

    const int NA4   = M_TOK * E_ / 4;
    const int NWIN4 = 3 * E_ * E_ / 4;
    const int NW4   = E_ * E_ / 4;

    // 1) split x and in_proj_w
    split_kernel<<<1024, 256>>>(x, th, tlp, NA4);
    split_kernel<<<1024, 256>>>(w_in, wh, wl, NWIN4);

    // 2) QKV GEMM -> bf16 hi/lo qkv, Q cols scaled by 1/8
    gemm_mma_split<<<dim3(3 * E_ / 128, M_TOK / 128), 256, GEMM_SMEM>>>(
        th, tlp, wh, wl, b_in, nullptr, qh, ql, M_TOK, 3 * E_, E_, 1, E_);

    // 3) flash attention -> att hi/lo
    attn_mma<<<dim3(T_ / 64, B_ * H_), 128, ATTN_SMEM>>>(qh, ql, ah, al);

    // 4) fused projection weight: Wf = Wc * Wo  (and fused bias)
    //    wh/wl[0..E2)     = Wo^T  (transposed split)
    //    wh/wl[E2..2E2)   = Wc
    //    wh/wl[2E2..3E2)  = Wf
    split_transpose_kernel<<<dim3(32, 32), dim3(32, 8)>>>(w_out, wh, wl);
    split_kernel<<<1024, 256>>>(w_c, wh + E2_, wl + E2_, NW4);
    bias_fuse_kernel<<<E_, 256>>>(w_c, b_out, b_c, biasf);
    gemm_mma_split<<<dim3(E_ / 128, E_ / 128), 256, GEMM_SMEM>>>(
        wh + E2_, wl + E2_, wh, wl, zerov, nullptr,
        wh + 2 * E2_, wl + 2 * E2_, E_, E_, E_, 1, 0);

    // 5) single fused output GEMM: out = att * Wf^T + biasf  (fp32)
    gemm_mma_split<<<dim3(E_ / 128, M_TOK / 128), 256, GEMM_SMEM>>>(
        ah, al, wh + 2 * E2_, wl + 2 * E2_, biasf, out, nullptr, nullptr,
        M_TOK, E_, E_, 0, 0);
}

// round 6
// speedup vs baseline: 3.0395x; 1.0067x over previous
#include <cuda_runtime.h>
#include <cuda_bf16.h>
#include <cstdint>
#include <cstddef>

// Problem constants
#define B_  8
#define T_  1024
#define E_  1024
#define H_  16
#define DH_ 64
#define M_TOK (B_ * T_)        // 8192 tokens
#define E2_ ((size_t)E_ * E_)

// ---------------------------------------------------------------------------
// Scratch (no cudaMalloc allowed -> __device__ globals)
// ---------------------------------------------------------------------------
__device__ __nv_bfloat16 g_qh[(size_t)M_TOK * 3 * E_];     // 48 MB  qkv hi
__device__ __nv_bfloat16 g_ql[(size_t)M_TOK * 3 * E_];     // 48 MB  qkv lo
__device__ __nv_bfloat16 g_ah[(size_t)M_TOK * E_];         // 16 MB  att hi
__device__ __nv_bfloat16 g_al[(size_t)M_TOK * E_];         // 16 MB  att lo
__device__ __nv_bfloat16 g_th[(size_t)M_TOK * E_];         // 16 MB  x hi
__device__ __nv_bfloat16 g_tl[(size_t)M_TOK * E_];         // 16 MB  x lo
__device__ __nv_bfloat16 g_wh[(size_t)3 * E_ * E_];        // 6 MB   weight hi
__device__ __nv_bfloat16 g_wl[(size_t)3 * E_ * E_];        // 6 MB   weight lo
__device__ float g_biasf[E_];                              // fused bias
__device__ float g_zero[E_];                               // zeros (.bss)

// ---------------------------------------------------------------------------
// PTX helpers (portable sm_80+ only; target is base sm_100)
// ---------------------------------------------------------------------------
__device__ __forceinline__ uint32_t smem_to_u32(const void* p) {
    uint32_t a;
    asm("{ .reg .u64 t; cvta.to.shared.u64 t, %1; cvt.u32.u64 %0, t; }"
        : "=r"(a) : "l"(p));
    return a;
}

#define CP_ASYNC16(dst, src) \
    asm volatile("cp.async.cg.shared.global [%0], [%1], 16;" \
                 :: "r"(dst), "l"(src) : "memory")
#define CP_COMMIT() asm volatile("cp.async.commit_group;" ::: "memory")
#define CP_WAIT(n)  asm volatile("cp.async.wait_group %0;" :: "n"(n) : "memory")

#define LDSM_X4(r, addr) \
    asm volatile("ldmatrix.sync.aligned.m8n8.x4.shared.b16 {%0,%1,%2,%3}, [%4];" \
                 : "=r"((r)[0]), "=r"((r)[1]), "=r"((r)[2]), "=r"((r)[3]) \
                 : "r"(addr))
#define LDSM_X2(r, addr) \
    asm volatile("ldmatrix.sync.aligned.m8n8.x2.shared.b16 {%0,%1}, [%2];" \
                 : "=r"((r)[0]), "=r"((r)[1]) : "r"(addr))
#define LDSM_X2T(r, addr) \
    asm volatile("ldmatrix.sync.aligned.m8n8.x2.trans.shared.b16 {%0,%1}, [%2];" \
                 : "=r"((r)[0]), "=r"((r)[1]) : "r"(addr))

#define MMA_BF16(c, a, b) \
    asm volatile("mma.sync.aligned.m16n8k16.row.col.f32.bf16.bf16.f32 " \
                 "{%0,%1,%2,%3}, {%4,%5,%6,%7}, {%8,%9}, {%0,%1,%2,%3};" \
                 : "+f"((c)[0]), "+f"((c)[1]), "+f"((c)[2]), "+f"((c)[3]) \
                 : "r"((a)[0]), "r"((a)[1]), "r"((a)[2]), "r"((a)[3]), \
                   "r"((b)[0]), "r"((b)[1]))

__device__ __forceinline__ uint32_t pack_bf(__nv_bfloat16 a, __nv_bfloat16 b) {
    __nv_bfloat162 t = __halves2bfloat162(a, b);
    return *reinterpret_cast<uint32_t*>(&t);
}

// split 2 floats into hi/lo bf16x2 words; returns hi, writes lo
__device__ __forceinline__ uint32_t pack_hi2(float x, float y, uint32_t& lo) {
    __nv_bfloat16 hx = __float2bfloat16_rn(x), hy = __float2bfloat16_rn(y);
    __nv_bfloat16 lx = __float2bfloat16_rn(x - __bfloat162float(hx));
    __nv_bfloat16 ly = __float2bfloat16_rn(y - __bfloat162float(hy));
    lo = pack_bf(lx, ly);
    return pack_bf(hx, hy);
}

// ---------------------------------------------------------------------------
// fp32 -> (bf16 hi, bf16 lo) split, vectorized
// ---------------------------------------------------------------------------
__global__ void split_kernel(const float* __restrict__ x,
                             __nv_bfloat16* __restrict__ hi,
                             __nv_bfloat16* __restrict__ lo, int n4) {
    int i = blockIdx.x * blockDim.x + threadIdx.x;
    int stride = gridDim.x * blockDim.x;
    for (; i < n4; i += stride) {
        float4 v = ((const float4*)x)[i];
        uint32_t l0, l1;
        uint32_t h0 = pack_hi2(v.x, v.y, l0);
        uint32_t h1 = pack_hi2(v.z, v.w, l1);
        ((uint2*)hi)[i] = make_uint2(h0, h1);
        ((uint2*)lo)[i] = make_uint2(l0, l1);
    }
}

// ---------------------------------------------------------------------------
// fp32 [E,E] -> transposed hi/lo bf16 [E,E] (out[i][j] = in[j][i])
// ---------------------------------------------------------------------------
__global__ void split_transpose_kernel(const float* __restrict__ x,
                                       __nv_bfloat16* __restrict__ hi,
                                       __nv_bfloat16* __restrict__ lo) {
    __shared__ float tile[32][33];
    const int bx = blockIdx.x * 32, by = blockIdx.y * 32;
    const int tx = threadIdx.x, ty = threadIdx.y;     // 32 x 8
#pragma unroll
    for (int u = 0; u < 4; u++)
        tile[ty + u * 8][tx] = x[(size_t)(by + ty + u * 8) * E_ + bx + tx];
    __syncthreads();
#pragma unroll
    for (int u = 0; u < 4; u++) {
        int r = ty + u * 8;
        float v = tile[tx][r];
        __nv_bfloat16 h = __float2bfloat16_rn(v);
        __nv_bfloat16 l = __float2bfloat16_rn(v - __bfloat162float(h));
        hi[(size_t)(bx + r) * E_ + by + tx] = h;
        lo[(size_t)(bx + r) * E_ + by + tx] = l;
    }
}

// ---------------------------------------------------------------------------
// fused bias: bf[n] = bc[n] + sum_k bo[k] * Wc[n,k]     (grid E_, block 256)
// ---------------------------------------------------------------------------
__global__ void bias_fuse_kernel(const float* __restrict__ wc,
                                 const float* __restrict__ bo,
                                 const float* __restrict__ bc,
                                 float* __restrict__ bf) {
    __shared__ float red[8];
    const int n = blockIdx.x, tid = threadIdx.x;
    float s = 0.f;
    for (int k = tid; k < E_; k += 256)
        s += wc[(size_t)n * E_ + k] * bo[k];
#pragma unroll
    for (int o = 16; o > 0; o >>= 1) s += __shfl_xor_sync(0xffffffffu, s, o);
    if ((tid & 31) == 0) red[tid >> 5] = s;
    __syncthreads();
    if (tid == 0) {
        float t = 0.f;
#pragma unroll
        for (int w = 0; w < 8; w++) t += red[w];
        bf[n] = t + bc[n];
    }
}

// ---------------------------------------------------------------------------
// mma.sync bf16 split GEMM: C = Ah*Bh^T + Ah*Bl^T + Al*Bh^T + bias
// out_bf16=0 -> Cf fp32;  out_bf16=1 -> (Ch,Cl) hi/lo bf16.
// cols < scale_cols get *0.125 (exact) -- folds 1/sqrt(dh) into Q.
// Block 128x128, 8 warps (64x32), KC=32, 3-stage cp.async pipeline,
// ONE __syncthreads per chunk (sync at iter c covers compute c-1, making
// stage (c+2)%3 == (c-1)%3 safe to overwrite).
// ---------------------------------------------------------------------------
#define KC 32
#define STAGE_B 32768
#define NSTAGE 3
#define GEMM_SMEM (NSTAGE * STAGE_B)

__global__ __launch_bounds__(256)
void gemm_mma_split(const __nv_bfloat16* __restrict__ Ah,
                    const __nv_bfloat16* __restrict__ Al,
                    const __nv_bfloat16* __restrict__ Bh,
                    const __nv_bfloat16* __restrict__ Bl,
                    const float* __restrict__ bias,
                    float* __restrict__ Cf,
                    __nv_bfloat16* __restrict__ Ch,
                    __nv_bfloat16* __restrict__ Cl,
                    int M, int N, int K, int out_bf16, int scale_cols)
{
    extern __shared__ char smem[];
    const uint32_t sbase = smem_to_u32(smem);
    const int tid  = threadIdx.x;
    const int wid  = tid >> 5;
    const int lane = tid & 31;
    const int warpM = (wid >> 2) * 64;
    const int warpN = (wid & 3) * 32;
    const int rowA = blockIdx.y * 128;
    const int rowB = blockIdx.x * 128;

    float acc[4][4][4];
#pragma unroll
    for (int mt = 0; mt < 4; mt++)
#pragma unroll
        for (int nt = 0; nt < 4; nt++)
#pragma unroll
            for (int r = 0; r < 4; r++) acc[mt][nt][r] = 0.f;

    const int idx0 = tid * 2;
    const int NC = K / KC;

    auto load_stage = [&](int c, int s) {
        const uint32_t sb = sbase + s * STAGE_B;
#pragma unroll
        for (int e = 0; e < 2; e++) {
            int idx  = idx0 + e;
            int row  = idx >> 2;
            int unit = idx & 3;
            uint32_t soff = (uint32_t)(row * 64 + ((unit ^ ((row >> 1) & 3)) << 4));
            size_t goffA = ((size_t)(rowA + row) * K + c * KC + unit * 8) * 2;
            size_t goffB = ((size_t)(rowB + row) * K + c * KC + unit * 8) * 2;
            CP_ASYNC16(sb + soff,         (const char*)Ah + goffA);
            CP_ASYNC16(sb +  8192 + soff, (const char*)Al + goffA);
            CP_ASYNC16(sb + 16384 + soff, (const char*)Bh + goffB);
            CP_ASYNC16(sb + 24576 + soff, (const char*)Bl + goffB);
        }
    };

    load_stage(0, 0);
    CP_COMMIT();
    if (NC > 1) { load_stage(1, 1); CP_COMMIT(); }

    const int a_row_in = (lane & 7) + ((lane >> 3) & 1) * 8;
    const int a_ksub   = (lane >> 4);
    const int tl       = lane & 15;
    const int b_row_in = tl & 7;
    const int b_ksub   = (tl >> 3) & 1;

    for (int c = 0; c < NC; c++) {
        // ensure chunk c's loads landed (pending may include chunk c+1)
        if (c + 1 < NC) CP_WAIT(1); else CP_WAIT(0);
        __syncthreads();   // all warps done computing chunk c-1

        // prefetch chunk c+2 into the stage computed at iter c-1 (now safe)
        if (c + 2 < NC) { load_stage(c + 2, (c + 2) % NSTAGE); CP_COMMIT(); }

        const uint32_t sb = sbase + (c % NSTAGE) * STAGE_B;

#pragma unroll
        for (int j = 0; j < 2; j++) {
            uint32_t aH[4][4], aL[4][4];
            uint32_t bH[4][2], bL[4][2];
            const int aunit = j * 2 + a_ksub;
            const int bunit = j * 2 + b_ksub;
#pragma unroll
            for (int mt = 0; mt < 4; mt++) {
                int row = warpM + mt * 16 + a_row_in;
                uint32_t xo = ((aunit ^ ((row >> 1) & 3)) << 4);
                LDSM_X4(aH[mt], sb + row * 64 + xo);
                LDSM_X4(aL[mt], sb + 8192 + row * 64 + xo);
            }
#pragma unroll
            for (int nt = 0; nt < 4; nt++) {
                int row = warpN + nt * 8 + b_row_in;
                uint32_t xo = ((bunit ^ ((row >> 1) & 3)) << 4);
                LDSM_X2(bH[nt], sb + 16384 + row * 64 + xo);
                LDSM_X2(bL[nt], sb + 24576 + row * 64 + xo);
            }
#pragma unroll
            for (int mt = 0; mt < 4; mt++)
#pragma unroll
                for (int nt = 0; nt < 4; nt++) {
                    MMA_BF16(acc[mt][nt], aH[mt], bH[nt]);
                    MMA_BF16(acc[mt][nt], aH[mt], bL[nt]);
                    MMA_BF16(acc[mt][nt], aL[mt], bH[nt]);
                }
        }
    }

    // epilogue
    const int erow = lane >> 2;
    const int ecol = (lane & 3) * 2;
#pragma unroll
    for (int mt = 0; mt < 4; mt++) {
#pragma unroll
        for (int nt = 0; nt < 4; nt++) {
            int gr = rowA + warpM + mt * 16 + erow;
            int gc = rowB + warpN + nt * 8 + ecol;
            float b0 = __ldg(bias + gc);
            float b1 = __ldg(bias + gc + 1);
            float sc = (gc < scale_cols) ? 0.125f : 1.0f;
            float v00 = (acc[mt][nt][0] + b0) * sc;
            float v01 = (acc[mt][nt][1] + b1) * sc;
            float v10 = (acc[mt][nt][2] + b0) * sc;
            float v11 = (acc[mt][nt][3] + b1) * sc;
            if (out_bf16) {
                uint32_t lo, hi;
                hi = pack_hi2(v00, v01, lo);
                *(uint32_t*)(Ch + (size_t)gr * N + gc) = hi;
                *(uint32_t*)(Cl + (size_t)gr * N + gc) = lo;
                hi = pack_hi2(v10, v11, lo);
                *(uint32_t*)(Ch + (size_t)(gr + 8) * N + gc) = hi;
                *(uint32_t*)(Cl + (size_t)(gr + 8) * N + gc) = lo;
            } else {
                *(float2*)(Cf + (size_t)gr * N + gc)       = make_float2(v00, v01);
                *(float2*)(Cf + (size_t)(gr + 8) * N + gc) = make_float2(v10, v11);
            }
        }
    }
}

// ---------------------------------------------------------------------------
// Flash attention with mma.sync bf16 split arithmetic.
// Q fragments hoisted out of the kt loop (Q smem is never overwritten).
// ---------------------------------------------------------------------------
#define ATTN_SMEM (16384 + 2 * 32768)

__global__ __launch_bounds__(128, 2)
void attn_mma(const __nv_bfloat16* __restrict__ qkvh,
              const __nv_bfloat16* __restrict__ qkvl,
              __nv_bfloat16* __restrict__ oh,
              __nv_bfloat16* __restrict__ ol)
{
    extern __shared__ char smem[];
    const uint32_t sbase = smem_to_u32(smem);
    const int tid  = threadIdx.x;
    const int lane = tid & 31;
    const int warp = tid >> 5;
    const int qt = blockIdx.x;
    const int bh = blockIdx.y;
    const int b = bh >> 4;
    const int h = bh & 15;

    const uint32_t sQh = sbase;
    const uint32_t sQl = sbase + 8192;

    const size_t tok0 = (size_t)b * T_;
    const size_t rs = 3 * E_;

    {
        const __nv_bfloat16* qb_h = qkvh + (tok0 + qt * 64) * rs + h * DH_;
        const __nv_bfloat16* qb_l = qkvl + (tok0 + qt * 64) * rs + h * DH_;
#pragma unroll
        for (int it = 0; it < 4; it++) {
            int idx = tid + it * 128;
            int row = idx >> 3, unit = idx & 7;
            uint32_t off = (uint32_t)(row * 128 + ((unit ^ (row & 7)) << 4));
            CP_ASYNC16(sQh + off, (const char*)(qb_h + (size_t)row * rs) + unit * 16);
            CP_ASYNC16(sQl + off, (const char*)(qb_l + (size_t)row * rs) + unit * 16);
        }
    }

    auto load_kv = [&](int kt, int s) {
        uint32_t sb = sbase + 16384 + s * 32768;
        const __nv_bfloat16* kh = qkvh + (tok0 + kt * 64) * rs + E_ + h * DH_;
        const __nv_bfloat16* kl = qkvl + (tok0 + kt * 64) * rs + E_ + h * DH_;
#pragma unroll
        for (int it = 0; it < 4; it++) {
            int idx = tid + it * 128;
            int row = idx >> 3, unit = idx & 7;
            uint32_t off = (uint32_t)(row * 128 + ((unit ^ (row & 7)) << 4));
            size_t g = (size_t)row * rs;
            CP_ASYNC16(sb +         off, (const char*)(kh + g) + unit * 16);
            CP_ASYNC16(sb +  8192 + off, (const char*)(kl + g) + unit * 16);
            CP_ASYNC16(sb + 16384 + off, (const char*)(kh + E_ + g) + unit * 16);
            CP_ASYNC16(sb + 24576 + off, (const char*)(kl + E_ + g) + unit * 16);
        }
    };

    load_kv(0, 0);
    CP_COMMIT();

    const int tl   = lane & 15;
    const int arow = warp * 16 + tl;
    const int aun  = lane >> 4;
    const int brw  = tl & 7;
    const int bks  = (tl >> 3) & 1;

    float O[8][4];
#pragma unroll
    for (int t = 0; t < 8; t++)
#pragma unroll
        for (int r = 0; r < 4; r++) O[t][r] = 0.f;
    float m0 = -1e30f, m1 = -1e30f, l0 = 0.f, l1 = 0.f;

    // hoisted Q fragments (loaded once after the first wait)
    uint32_t qH[4][4], qL[4][4];
    bool qloaded = false;

    for (int kt = 0; kt <= qt; kt++) {
        CP_WAIT(0);
        __syncthreads();
        if (kt < qt) { load_kv(kt + 1, (kt + 1) & 1); CP_COMMIT(); }

        if (!qloaded) {
            qloaded = true;
#pragma unroll
            for (int j = 0; j < 4; j++) {
                int au = j * 2 + aun;
                uint32_t aoff = (uint32_t)(arow * 128 + ((au ^ (arow & 7)) << 4));
                LDSM_X4(qH[j], sQh + aoff);
                LDSM_X4(qL[j], sQl + aoff);
            }
        }

        const uint32_t sb  = sbase + 16384 + (kt & 1) * 32768;
        const uint32_t sKh = sb, sKl = sb + 8192;
        const uint32_t sVh = sb + 16384, sVl = sb + 24576;

        float S[8][4];
#pragma unroll
        for (int t = 0; t < 8; t++)
#pragma unroll
            for (int r = 0; r < 4; r++) S[t][r] = 0.f;

#pragma unroll
        for (int j = 0; j < 4; j++) {
#pragma unroll
            for (int t = 0; t < 8; t++) {
                int r = t * 8 + brw;
                int u = j * 2 + bks;
                uint32_t boff = (uint32_t)(r * 128 + ((u ^ (r & 7)) << 4));
                uint32_t bH[2], bL[2];
                LDSM_X2(bH, sKh + boff);
                LDSM_X2(bL, sKl + boff);
                MMA_BF16(S[t], qH[j], bH);
                MMA_BF16(S[t], qH[j], bL);
                MMA_BF16(S[t], qL[j], bH);
            }
        }

        if (kt == qt) {
            int r0 = warp * 16 + (lane >> 2);
#pragma unroll
            for (int t = 0; t < 8; t++) {
                int c = t * 8 + (lane & 3) * 2;
                if (c     > r0)     S[t][0] = -1e30f;
                if (c + 1 > r0)     S[t][1] = -1e30f;
                if (c     > r0 + 8) S[t][2] = -1e30f;
                if (c + 1 > r0 + 8) S[t][3] = -1e30f;
            }
        }

        float rm0 = -1e30f, rm1 = -1e30f;
#pragma unroll
        for (int t = 0; t < 8; t++) {
            rm0 = fmaxf(rm0, fmaxf(S[t][0], S[t][1]));
            rm1 = fmaxf(rm1, fmaxf(S[t][2], S[t][3]));
        }
        rm0 = fmaxf(rm0, __shfl_xor_sync(0xffffffffu, rm0, 1));
        rm0 = fmaxf(rm0, __shfl_xor_sync(0xffffffffu, rm0, 2));
        rm1 = fmaxf(rm1, __shfl_xor_sync(0xffffffffu, rm1, 1));
        rm1 = fmaxf(rm1, __shfl_xor_sync(0xffffffffu, rm1, 2));
        float mn0 = fmaxf(m0, rm0), mn1 = fmaxf(m1, rm1);
        float al0 = __expf(m0 - mn0), al1 = __expf(m1 - mn1);
        m0 = mn0; m1 = mn1;

        float ls0 = 0.f, ls1 = 0.f;
#pragma unroll
        for (int t = 0; t < 8; t++) {
            S[t][0] = __expf(S[t][0] - mn0); ls0 += S[t][0];
            S[t][1] = __expf(S[t][1] - mn0); ls0 += S[t][1];
            S[t][2] = __expf(S[t][2] - mn1); ls1 += S[t][2];
            S[t][3] = __expf(S[t][3] - mn1); ls1 += S[t][3];
        }
        l0 = l0 * al0 + ls0;
        l1 = l1 * al1 + ls1;
#pragma unroll
        for (int t = 0; t < 8; t++) {
            O[t][0] *= al0; O[t][1] *= al0;
            O[t][2] *= al1; O[t][3] *= al1;
        }

        uint32_t pH[4][4], pL[4][4];
#pragma unroll
        for (int j = 0; j < 4; j++) {
            pH[j][0] = pack_hi2(S[2*j][0],   S[2*j][1],   pL[j][0]);
            pH[j][1] = pack_hi2(S[2*j][2],   S[2*j][3],   pL[j][1]);
            pH[j][2] = pack_hi2(S[2*j+1][0], S[2*j+1][1], pL[j][2]);
            pH[j][3] = pack_hi2(S[2*j+1][2], S[2*j+1][3], pL[j][3]);
        }

#pragma unroll
        for (int j = 0; j < 4; j++) {
            int vr = j * 16 + brw + bks * 8;
#pragma unroll
            for (int t = 0; t < 8; t++) {
                uint32_t voff = (uint32_t)(vr * 128 + ((t ^ (vr & 7)) << 4));
                uint32_t vH[2], vL[2];
                LDSM_X2T(vH, sVh + voff);
                LDSM_X2T(vL, sVl + voff);
                MMA_BF16(O[t], pH[j], vH);
                MMA_BF16(O[t], pL[j], vH);
                MMA_BF16(O[t], pH[j], vL);
            }
        }
    }

    l0 += __shfl_xor_sync(0xffffffffu, l0, 1);
    l0 += __shfl_xor_sync(0xffffffffu, l0, 2);
    l1 += __shfl_xor_sync(0xffffffffu, l1, 1);
    l1 += __shfl_xor_sync(0xffffffffu, l1, 2);
    float inv0 = 1.f / l0, inv1 = 1.f / l1;

    int r0 = qt * 64 + warp * 16 + (lane >> 2);
    size_t grow0 = (tok0 + r0) * E_ + h * DH_;
    size_t grow1 = grow0 + (size_t)8 * E_;
#pragma unroll
    for (int t = 0; t < 8; t++) {
        int c = t * 8 + (lane & 3) * 2;
        uint32_t lo, hi;
        hi = pack_hi2(O[t][0] * inv0, O[t][1] * inv0, lo);
        *(uint32_t*)(oh + grow0 + c) = hi;
        *(uint32_t*)(ol + grow0 + c) = lo;
        hi = pack_hi2(O[t][2] * inv1, O[t][3] * inv1, lo);
        *(uint32_t*)(oh + grow1 + c) = hi;
        *(uint32_t*)(ol + grow1 + c) = lo;
    }
}

// ---------------------------------------------------------------------------
// kernel_launch
// inputs: x, in_proj_w, in_proj_b, out_proj_w, out_proj_b, c_proj_w, c_proj_b
// ---------------------------------------------------------------------------
extern "C" void kernel_launch(void* const* d_in, const int* in_sizes, int n_in,
                              void* d_out, int out_size)
{
    const float* x     = (const float*)d_in[0];
    const float* w_in  = (const float*)d_in[1];
    const float* b_in  = (const float*)d_in[2];
    const float* w_out = (const float*)d_in[3];
    const float* b_out = (const float*)d_in[4];
    const float* w_c   = (const float*)d_in[5];
    const float* b_c   = (const float*)d_in[6];
    float* out = (float*)d_out;

    __nv_bfloat16 *qh, *ql, *ah, *al, *th, *tlp, *wh, *wl;
    float *biasf, *zerov;
    cudaGetSymbolAddress((void**)&qh, g_qh);
    cudaGetSymbolAddress((void**)&ql, g_ql);
    cudaGetSymbolAddress((void**)&ah, g_ah);
    cudaGetSymbolAddress((void**)&al, g_al);
    cudaGetSymbolAddress((void**)&th, g_th);
    cudaGetSymbolAddress((void**)&tlp, g_tl);
    cudaGetSymbolAddress((void**)&wh, g_wh);
    cudaGetSymbolAddress((void**)&wl, g_wl);
    cudaGetSymbolAddress((void**)&biasf, g_biasf);
    cudaGetSymbolAddress((void**)&zerov, g_zero);

    cudaFuncSetAttribute(gemm_mma_split,
                         cudaFuncAttributeMaxDynamicSharedMemorySize, GEMM_SMEM);
    cudaFuncSetAttribute(attn_mma,
                         cudaFuncAttributeMaxDynamicSharedMemorySize, ATTN_SMEM);

    const int NA4   = M_TOK * E_ / 4;
    const int NWIN4 = 3 * E_ * E_ / 4;
    const int NW4   = E_ * E_ / 4;

    // 1) split x and in_proj_w
    split_kernel<<<1024, 256>>>(x, th, tlp, NA4);
    split_kernel<<<1024, 256>>>(w_in, wh, wl, NWIN4);

    // 2) QKV GEMM -> bf16 hi/lo qkv, Q cols scaled by 1/8
    gemm_mma_split<<<dim3(3 * E_ / 128, M_TOK / 128), 256, GEMM_SMEM>>>(
        th, tlp, wh, wl, b_in, nullptr, qh, ql, M_TOK, 3 * E_, E_, 1, E_);

    // 3) flash attention -> att hi/lo
    attn_mma<<<dim3(T_ / 64, B_ * H_), 128, ATTN_SMEM>>>(qh, ql, ah, al);

    // 4) fused projection weight: Wf = Wc * Wo  (and fused bias)
    split_transpose_kernel<<<dim3(32, 32), dim3(32, 8)>>>(w_out, wh, wl);
    split_kernel<<<1024, 256>>>(w_c, wh + E2_, wl + E2_, NW4);
    bias_fuse_kernel<<<E_, 256>>>(w_c, b_out, b_c, biasf);
    gemm_mma_split<<<dim3(E_ / 128, E_ / 128), 256, GEMM_SMEM>>>(
        wh + E2_, wl + E2_, wh, wl, zerov, nullptr,
        wh + 2 * E2_, wl + 2 * E2_, E_, E_, E_, 1, 0);

    // 5) single fused output GEMM: out = att * Wf^T + biasf  (fp32)
    gemm_mma_split<<<dim3(E_ / 128, M_TOK / 128), 256, GEMM_SMEM>>>(
        ah, al, wh + 2 * E2_, wl + 2 * E2_, biasf, out, nullptr, nullptr,
        M_TOK, E_, E_, 0, 0);
}

// round 7
// speedup vs baseline: 4.0528x; 1.3334x over previous
#include <cuda_runtime.h>
#include <cuda_fp16.h>
#include <cstdint>
#include <cstddef>

// Problem constants
#define B_  8
#define T_  1024
#define E_  1024
#define H_  16
#define DH_ 64
#define M_TOK (B_ * T_)        // 8192 tokens
#define E2_ ((size_t)E_ * E_)

// ---------------------------------------------------------------------------
// Scratch (no cudaMalloc allowed -> __device__ globals)
// ---------------------------------------------------------------------------
__device__ __half g_qh[(size_t)M_TOK * 3 * E_];     // 48 MB  qkv hi (k/v single)
__device__ __half g_ql[(size_t)M_TOK * 3 * E_];     // 48 MB  qkv lo (Q only used)
__device__ __half g_ah[(size_t)M_TOK * E_];         // 16 MB  att hi
__device__ __half g_al[(size_t)M_TOK * E_];         // 16 MB  att lo
__device__ __half g_th[(size_t)M_TOK * E_];         // 16 MB  x hi
__device__ __half g_tl[(size_t)M_TOK * E_];         // 16 MB  x lo
__device__ __half g_wh[(size_t)3 * E_ * E_];        // 6 MB   weights (single fp16)
__device__ __half g_wl[(size_t)2 * E_ * E_];        // 4 MB   Wc hi/lo
__device__ float g_biasf[E_];                       // fused bias
__device__ float g_zero[E_];                        // zeros (.bss)

// ---------------------------------------------------------------------------
// PTX helpers (portable sm_80+ only; target is base sm_100)
// ---------------------------------------------------------------------------
__device__ __forceinline__ uint32_t smem_to_u32(const void* p) {
    uint32_t a;
    asm("{ .reg .u64 t; cvta.to.shared.u64 t, %1; cvt.u32.u64 %0, t; }"
        : "=r"(a) : "l"(p));
    return a;
}

#define CP_ASYNC16(dst, src) \
    asm volatile("cp.async.cg.shared.global [%0], [%1], 16;" \
                 :: "r"(dst), "l"(src) : "memory")
#define CP_COMMIT() asm volatile("cp.async.commit_group;" ::: "memory")
#define CP_WAIT(n)  asm volatile("cp.async.wait_group %0;" :: "n"(n) : "memory")

#define LDSM_X4(r, addr) \
    asm volatile("ldmatrix.sync.aligned.m8n8.x4.shared.b16 {%0,%1,%2,%3}, [%4];" \
                 : "=r"((r)[0]), "=r"((r)[1]), "=r"((r)[2]), "=r"((r)[3]) \
                 : "r"(addr))
#define LDSM_X2(r, addr) \
    asm volatile("ldmatrix.sync.aligned.m8n8.x2.shared.b16 {%0,%1}, [%2];" \
                 : "=r"((r)[0]), "=r"((r)[1]) : "r"(addr))
#define LDSM_X2T(r, addr) \
    asm volatile("ldmatrix.sync.aligned.m8n8.x2.trans.shared.b16 {%0,%1}, [%2];" \
                 : "=r"((r)[0]), "=r"((r)[1]) : "r"(addr))

#define MMA_F16(c, a, b) \
    asm volatile("mma.sync.aligned.m16n8k16.row.col.f32.f16.f16.f32 " \
                 "{%0,%1,%2,%3}, {%4,%5,%6,%7}, {%8,%9}, {%0,%1,%2,%3};" \
                 : "+f"((c)[0]), "+f"((c)[1]), "+f"((c)[2]), "+f"((c)[3]) \
                 : "r"((a)[0]), "r"((a)[1]), "r"((a)[2]), "r"((a)[3]), \
                   "r"((b)[0]), "r"((b)[1]))

__device__ __forceinline__ uint32_t pack_h2(__half a, __half b) {
    __half2 t = __halves2half2(a, b);
    return *reinterpret_cast<uint32_t*>(&t);
}

// split 2 floats into hi/lo fp16x2 words; returns hi, writes lo
__device__ __forceinline__ uint32_t pack_hi2(float x, float y, uint32_t& lo) {
    __half hx = __float2half_rn(x), hy = __float2half_rn(y);
    __half lx = __float2half_rn(x - __half2float(hx));
    __half ly = __float2half_rn(y - __half2float(hy));
    lo = pack_h2(lx, ly);
    return pack_h2(hx, hy);
}

// ---------------------------------------------------------------------------
// fp32 -> (fp16 hi, fp16 lo) split, vectorized
// ---------------------------------------------------------------------------
__global__ void split_kernel(const float* __restrict__ x,
                             __half* __restrict__ hi,
                             __half* __restrict__ lo, int n4) {
    int i = blockIdx.x * blockDim.x + threadIdx.x;
    int stride = gridDim.x * blockDim.x;
    for (; i < n4; i += stride) {
        float4 v = ((const float4*)x)[i];
        uint32_t l0, l1;
        uint32_t h0 = pack_hi2(v.x, v.y, l0);
        uint32_t h1 = pack_hi2(v.z, v.w, l1);
        ((uint2*)hi)[i] = make_uint2(h0, h1);
        ((uint2*)lo)[i] = make_uint2(l0, l1);
    }
}

// fp32 -> single fp16 convert
__global__ void convert_kernel(const float* __restrict__ x,
                               __half* __restrict__ hi, int n4) {
    int i = blockIdx.x * blockDim.x + threadIdx.x;
    int stride = gridDim.x * blockDim.x;
    for (; i < n4; i += stride) {
        float4 v = ((const float4*)x)[i];
        ((uint2*)hi)[i] = make_uint2(
            pack_h2(__float2half_rn(v.x), __float2half_rn(v.y)),
            pack_h2(__float2half_rn(v.z), __float2half_rn(v.w)));
    }
}

// ---------------------------------------------------------------------------
// fp32 [E,E] -> transposed single fp16 [E,E] (out[i][j] = in[j][i])
// ---------------------------------------------------------------------------
__global__ void transpose_convert_kernel(const float* __restrict__ x,
                                         __half* __restrict__ hi) {
    __shared__ float tile[32][33];
    const int bx = blockIdx.x * 32, by = blockIdx.y * 32;
    const int tx = threadIdx.x, ty = threadIdx.y;     // 32 x 8
#pragma unroll
    for (int u = 0; u < 4; u++)
        tile[ty + u * 8][tx] = x[(size_t)(by + ty + u * 8) * E_ + bx + tx];
    __syncthreads();
#pragma unroll
    for (int u = 0; u < 4; u++) {
        int r = ty + u * 8;
        hi[(size_t)(bx + r) * E_ + by + tx] = __float2half_rn(tile[tx][r]);
    }
}

// ---------------------------------------------------------------------------
// fused bias: bf[n] = bc[n] + sum_k bo[k] * Wc[n,k]     (grid E_, block 256)
// ---------------------------------------------------------------------------
__global__ void bias_fuse_kernel(const float* __restrict__ wc,
                                 const float* __restrict__ bo,
                                 const float* __restrict__ bc,
                                 float* __restrict__ bf) {
    __shared__ float red[8];
    const int n = blockIdx.x, tid = threadIdx.x;
    float s = 0.f;
    for (int k = tid; k < E_; k += 256)
        s += wc[(size_t)n * E_ + k] * bo[k];
#pragma unroll
    for (int o = 16; o > 0; o >>= 1) s += __shfl_xor_sync(0xffffffffu, s, o);
    if ((tid & 31) == 0) red[tid >> 5] = s;
    __syncthreads();
    if (tid == 0) {
        float t = 0.f;
#pragma unroll
        for (int w = 0; w < 8; w++) t += red[w];
        bf[n] = t + bc[n];
    }
}

// ---------------------------------------------------------------------------
// fp16 2-term split GEMM: C = (Ah + Al) * B^T + bias
// A: [M,K] fp16 hi/lo. B: [N,K] single fp16.
// out_f16=0 -> Cf fp32;  out_f16=1 -> Ch hi (+ Cl lo for cols < lo_cols).
// cols < scale_cols get *0.125 (exact) -- folds 1/sqrt(dh) into Q.
// Block 128x128, 8 warps (64x32), KC=32, 3-stage cp.async, 1 sync/chunk.
// stage layout: Ah[0,8K) | Al[8K,16K) | B[16K,24K)
// ---------------------------------------------------------------------------
#define KC 32
#define STAGE_B 24576
#define NSTAGE 3
#define GEMM_SMEM (NSTAGE * STAGE_B)   // 73728

__global__ __launch_bounds__(256)
void gemm_mma_split(const __half* __restrict__ Ah,
                    const __half* __restrict__ Al,
                    const __half* __restrict__ Bs,
                    const float* __restrict__ bias,
                    float* __restrict__ Cf,
                    __half* __restrict__ Ch,
                    __half* __restrict__ Cl,
                    int M, int N, int K, int out_f16, int scale_cols,
                    int lo_cols)
{
    extern __shared__ char smem[];
    const uint32_t sbase = smem_to_u32(smem);
    const int tid  = threadIdx.x;
    const int wid  = tid >> 5;
    const int lane = tid & 31;
    const int warpM = (wid >> 2) * 64;
    const int warpN = (wid & 3) * 32;
    const int rowA = blockIdx.y * 128;
    const int rowB = blockIdx.x * 128;

    float acc[4][4][4];
#pragma unroll
    for (int mt = 0; mt < 4; mt++)
#pragma unroll
        for (int nt = 0; nt < 4; nt++)
#pragma unroll
            for (int r = 0; r < 4; r++) acc[mt][nt][r] = 0.f;

    const int idx0 = tid * 2;
    const int NC = K / KC;

    auto load_stage = [&](int c, int s) {
        const uint32_t sb = sbase + s * STAGE_B;
#pragma unroll
        for (int e = 0; e < 2; e++) {
            int idx  = idx0 + e;
            int row  = idx >> 2;
            int unit = idx & 3;
            uint32_t soff = (uint32_t)(row * 64 + ((unit ^ ((row >> 1) & 3)) << 4));
            size_t goffA = ((size_t)(rowA + row) * K + c * KC + unit * 8) * 2;
            size_t goffB = ((size_t)(rowB + row) * K + c * KC + unit * 8) * 2;
            CP_ASYNC16(sb + soff,         (const char*)Ah + goffA);
            CP_ASYNC16(sb +  8192 + soff, (const char*)Al + goffA);
            CP_ASYNC16(sb + 16384 + soff, (const char*)Bs + goffB);
        }
    };

    load_stage(0, 0);
    CP_COMMIT();
    if (NC > 1) { load_stage(1, 1); CP_COMMIT(); }

    const int a_row_in = (lane & 7) + ((lane >> 3) & 1) * 8;
    const int a_ksub   = (lane >> 4);
    const int tl       = lane & 15;
    const int b_row_in = tl & 7;
    const int b_ksub   = (tl >> 3) & 1;

    for (int c = 0; c < NC; c++) {
        if (c + 1 < NC) CP_WAIT(1); else CP_WAIT(0);
        __syncthreads();

        if (c + 2 < NC) { load_stage(c + 2, (c + 2) % NSTAGE); CP_COMMIT(); }

        const uint32_t sb = sbase + (c % NSTAGE) * STAGE_B;

#pragma unroll
        for (int j = 0; j < 2; j++) {
            uint32_t aH[4][4], aL[4][4];
            uint32_t bF[4][2];
            const int aunit = j * 2 + a_ksub;
            const int bunit = j * 2 + b_ksub;
#pragma unroll
            for (int mt = 0; mt < 4; mt++) {
                int row = warpM + mt * 16 + a_row_in;
                uint32_t xo = ((aunit ^ ((row >> 1) & 3)) << 4);
                LDSM_X4(aH[mt], sb + row * 64 + xo);
                LDSM_X4(aL[mt], sb + 8192 + row * 64 + xo);
            }
#pragma unroll
            for (int nt = 0; nt < 4; nt++) {
                int row = warpN + nt * 8 + b_row_in;
                uint32_t xo = ((bunit ^ ((row >> 1) & 3)) << 4);
                LDSM_X2(bF[nt], sb + 16384 + row * 64 + xo);
            }
#pragma unroll
            for (int mt = 0; mt < 4; mt++)
#pragma unroll
                for (int nt = 0; nt < 4; nt++) {
                    MMA_F16(acc[mt][nt], aH[mt], bF[nt]);
                    MMA_F16(acc[mt][nt], aL[mt], bF[nt]);
                }
        }
    }

    // epilogue
    const int erow = lane >> 2;
    const int ecol = (lane & 3) * 2;
#pragma unroll
    for (int mt = 0; mt < 4; mt++) {
#pragma unroll
        for (int nt = 0; nt < 4; nt++) {
            int gr = rowA + warpM + mt * 16 + erow;
            int gc = rowB + warpN + nt * 8 + ecol;
            float b0 = __ldg(bias + gc);
            float b1 = __ldg(bias + gc + 1);
            float sc = (gc < scale_cols) ? 0.125f : 1.0f;
            float v00 = (acc[mt][nt][0] + b0) * sc;
            float v01 = (acc[mt][nt][1] + b1) * sc;
            float v10 = (acc[mt][nt][2] + b0) * sc;
            float v11 = (acc[mt][nt][3] + b1) * sc;
            if (out_f16) {
                uint32_t lo0, lo1, hi0, hi1;
                hi0 = pack_hi2(v00, v01, lo0);
                hi1 = pack_hi2(v10, v11, lo1);
                *(uint32_t*)(Ch + (size_t)gr * N + gc)       = hi0;
                *(uint32_t*)(Ch + (size_t)(gr + 8) * N + gc) = hi1;
                if (gc < lo_cols) {
                    *(uint32_t*)(Cl + (size_t)gr * N + gc)       = lo0;
                    *(uint32_t*)(Cl + (size_t)(gr + 8) * N + gc) = lo1;
                }
            } else {
                *(float2*)(Cf + (size_t)gr * N + gc)       = make_float2(v00, v01);
                *(float2*)(Cf + (size_t)(gr + 8) * N + gc) = make_float2(v10, v11);
            }
        }
    }
}

// ---------------------------------------------------------------------------
// Flash attention, fp16 2-term split: S = (Qh+Ql)K, O = (Ph+Pl)V.
// K and V consumed as single fp16 (the hi plane). Q fragments hoisted.
// smem: Qh|Ql (16 KB) + 2 stages x (K|V = 16 KB) = 48 KB.
// ---------------------------------------------------------------------------
#define ATTN_SMEM (16384 + 2 * 16384)

__global__ __launch_bounds__(128, 2)
void attn_mma(const __half* __restrict__ qkvh,
              const __half* __restrict__ qkvl,
              __half* __restrict__ oh,
              __half* __restrict__ ol)
{
    extern __shared__ char smem[];
    const uint32_t sbase = smem_to_u32(smem);
    const int tid  = threadIdx.x;
    const int lane = tid & 31;
    const int warp = tid >> 5;
    const int qt = blockIdx.x;
    const int bh = blockIdx.y;
    const int b = bh >> 4;
    const int h = bh & 15;

    const uint32_t sQh = sbase;
    const uint32_t sQl = sbase + 8192;

    const size_t tok0 = (size_t)b * T_;
    const size_t rs = 3 * E_;

    {
        const __half* qb_h = qkvh + (tok0 + qt * 64) * rs + h * DH_;
        const __half* qb_l = qkvl + (tok0 + qt * 64) * rs + h * DH_;
#pragma unroll
        for (int it = 0; it < 4; it++) {
            int idx = tid + it * 128;
            int row = idx >> 3, unit = idx & 7;
            uint32_t off = (uint32_t)(row * 128 + ((unit ^ (row & 7)) << 4));
            CP_ASYNC16(sQh + off, (const char*)(qb_h + (size_t)row * rs) + unit * 16);
            CP_ASYNC16(sQl + off, (const char*)(qb_l + (size_t)row * rs) + unit * 16);
        }
    }

    auto load_kv = [&](int kt, int s) {
        uint32_t sb = sbase + 16384 + s * 16384;
        const __half* kh = qkvh + (tok0 + kt * 64) * rs + E_ + h * DH_;
#pragma unroll
        for (int it = 0; it < 4; it++) {
            int idx = tid + it * 128;
            int row = idx >> 3, unit = idx & 7;
            uint32_t off = (uint32_t)(row * 128 + ((unit ^ (row & 7)) << 4));
            size_t g = (size_t)row * rs;
            CP_ASYNC16(sb +        off, (const char*)(kh + g) + unit * 16);
            CP_ASYNC16(sb + 8192 + off, (const char*)(kh + E_ + g) + unit * 16);
        }
    };

    load_kv(0, 0);
    CP_COMMIT();

    const int tl   = lane & 15;
    const int arow = warp * 16 + tl;
    const int aun  = lane >> 4;
    const int brw  = tl & 7;
    const int bks  = (tl >> 3) & 1;

    float O[8][4];
#pragma unroll
    for (int t = 0; t < 8; t++)
#pragma unroll
        for (int r = 0; r < 4; r++) O[t][r] = 0.f;
    float m0 = -1e30f, m1 = -1e30f, l0 = 0.f, l1 = 0.f;

    uint32_t qH[4][4], qL[4][4];
    bool qloaded = false;

    for (int kt = 0; kt <= qt; kt++) {
        CP_WAIT(0);
        __syncthreads();
        if (kt < qt) { load_kv(kt + 1, (kt + 1) & 1); CP_COMMIT(); }

        if (!qloaded) {
            qloaded = true;
#pragma unroll
            for (int j = 0; j < 4; j++) {
                int au = j * 2 + aun;
                uint32_t aoff = (uint32_t)(arow * 128 + ((au ^ (arow & 7)) << 4));
                LDSM_X4(qH[j], sQh + aoff);
                LDSM_X4(qL[j], sQl + aoff);
            }
        }

        const uint32_t sb = sbase + 16384 + (kt & 1) * 16384;
        const uint32_t sK = sb, sV = sb + 8192;

        float S[8][4];
#pragma unroll
        for (int t = 0; t < 8; t++)
#pragma unroll
            for (int r = 0; r < 4; r++) S[t][r] = 0.f;

#pragma unroll
        for (int j = 0; j < 4; j++) {
#pragma unroll
            for (int t = 0; t < 8; t++) {
                int r = t * 8 + brw;
                int u = j * 2 + bks;
                uint32_t boff = (uint32_t)(r * 128 + ((u ^ (r & 7)) << 4));
                uint32_t bF[2];
                LDSM_X2(bF, sK + boff);
                MMA_F16(S[t], qH[j], bF);
                MMA_F16(S[t], qL[j], bF);
            }
        }

        if (kt == qt) {
            int r0 = warp * 16 + (lane >> 2);
#pragma unroll
            for (int t = 0; t < 8; t++) {
                int c = t * 8 + (lane & 3) * 2;
                if (c     > r0)     S[t][0] = -1e30f;
                if (c + 1 > r0)     S[t][1] = -1e30f;
                if (c     > r0 + 8) S[t][2] = -1e30f;
                if (c + 1 > r0 + 8) S[t][3] = -1e30f;
            }
        }

        float rm0 = -1e30f, rm1 = -1e30f;
#pragma unroll
        for (int t = 0; t < 8; t++) {
            rm0 = fmaxf(rm0, fmaxf(S[t][0], S[t][1]));
            rm1 = fmaxf(rm1, fmaxf(S[t][2], S[t][3]));
        }
        rm0 = fmaxf(rm0, __shfl_xor_sync(0xffffffffu, rm0, 1));
        rm0 = fmaxf(rm0, __shfl_xor_sync(0xffffffffu, rm0, 2));
        rm1 = fmaxf(rm1, __shfl_xor_sync(0xffffffffu, rm1, 1));
        rm1 = fmaxf(rm1, __shfl_xor_sync(0xffffffffu, rm1, 2));
        float mn0 = fmaxf(m0, rm0), mn1 = fmaxf(m1, rm1);
        float al0 = __expf(m0 - mn0), al1 = __expf(m1 - mn1);
        m0 = mn0; m1 = mn1;

        float ls0 = 0.f, ls1 = 0.f;
#pragma unroll
        for (int t = 0; t < 8; t++) {
            S[t][0] = __expf(S[t][0] - mn0); ls0 += S[t][0];
            S[t][1] = __expf(S[t][1] - mn0); ls0 += S[t][1];
            S[t][2] = __expf(S[t][2] - mn1); ls1 += S[t][2];
            S[t][3] = __expf(S[t][3] - mn1); ls1 += S[t][3];
        }
        l0 = l0 * al0 + ls0;
        l1 = l1 * al1 + ls1;
#pragma unroll
        for (int t = 0; t < 8; t++) {
            O[t][0] *= al0; O[t][1] *= al0;
            O[t][2] *= al1; O[t][3] *= al1;
        }

        uint32_t pH[4][4], pL[4][4];
#pragma unroll
        for (int j = 0; j < 4; j++) {
            pH[j][0] = pack_hi2(S[2*j][0],   S[2*j][1],   pL[j][0]);
            pH[j][1] = pack_hi2(S[2*j][2],   S[2*j][3],   pL[j][1]);
            pH[j][2] = pack_hi2(S[2*j+1][0], S[2*j+1][1], pL[j][2]);
            pH[j][3] = pack_hi2(S[2*j+1][2], S[2*j+1][3], pL[j][3]);
        }

#pragma unroll
        for (int j = 0; j < 4; j++) {
            int vr = j * 16 + brw + bks * 8;
#pragma unroll
            for (int t = 0; t < 8; t++) {
                uint32_t voff = (uint32_t)(vr * 128 + ((t ^ (vr & 7)) << 4));
                uint32_t vF[2];
                LDSM_X2T(vF, sV + voff);
                MMA_F16(O[t], pH[j], vF);
                MMA_F16(O[t], pL[j], vF);
            }
        }
    }

    l0 += __shfl_xor_sync(0xffffffffu, l0, 1);
    l0 += __shfl_xor_sync(0xffffffffu, l0, 2);
    l1 += __shfl_xor_sync(0xffffffffu, l1, 1);
    l1 += __shfl_xor_sync(0xffffffffu, l1, 2);
    float inv0 = 1.f / l0, inv1 = 1.f / l1;

    int r0 = qt * 64 + warp * 16 + (lane >> 2);
    size_t grow0 = (tok0 + r0) * E_ + h * DH_;
    size_t grow1 = grow0 + (size_t)8 * E_;
#pragma unroll
    for (int t = 0; t < 8; t++) {
        int c = t * 8 + (lane & 3) * 2;
        uint32_t lo, hi;
        hi = pack_hi2(O[t][0] * inv0, O[t][1] * inv0, lo);
        *(uint32_t*)(oh + grow0 + c) = hi;
        *(uint32_t*)(ol + grow0 + c) = lo;
        hi = pack_hi2(O[t][2] * inv1, O[t][3] * inv1, lo);
        *(uint32_t*)(oh + grow1 + c) = hi;
        *(uint32_t*)(ol + grow1 + c) = lo;
    }
}

// ---------------------------------------------------------------------------
// kernel_launch
// inputs: x, in_proj_w, in_proj_b, out_proj_w, out_proj_b, c_proj_w, c_proj_b
// ---------------------------------------------------------------------------
extern "C" void kernel_launch(void* const* d_in, const int* in_sizes, int n_in,
                              void* d_out, int out_size)
{
    const float* x     = (const float*)d_in[0];
    const float* w_in  = (const float*)d_in[1];
    const float* b_in  = (const float*)d_in[2];
    const float* w_out = (const float*)d_in[3];
    const float* b_out = (const float*)d_in[4];
    const float* w_c   = (const float*)d_in[5];
    const float* b_c   = (const float*)d_in[6];
    float* out = (float*)d_out;

    __half *qh, *ql, *ah, *al, *th, *tlp, *wh, *wl;
    float *biasf, *zerov;
    cudaGetSymbolAddress((void**)&qh, g_qh);
    cudaGetSymbolAddress((void**)&ql, g_ql);
    cudaGetSymbolAddress((void**)&ah, g_ah);
    cudaGetSymbolAddress((void**)&al, g_al);
    cudaGetSymbolAddress((void**)&th, g_th);
    cudaGetSymbolAddress((void**)&tlp, g_tl);
    cudaGetSymbolAddress((void**)&wh, g_wh);
    cudaGetSymbolAddress((void**)&wl, g_wl);
    cudaGetSymbolAddress((void**)&biasf, g_biasf);
    cudaGetSymbolAddress((void**)&zerov, g_zero);

    cudaFuncSetAttribute(gemm_mma_split,
                         cudaFuncAttributeMaxDynamicSharedMemorySize, GEMM_SMEM);
    cudaFuncSetAttribute(attn_mma,
                         cudaFuncAttributeMaxDynamicSharedMemorySize, ATTN_SMEM);

    const int NA4   = M_TOK * E_ / 4;
    const int NWIN4 = 3 * E_ * E_ / 4;
    const int NW4   = E_ * E_ / 4;

    // 1) split x (A side) and convert in_proj_w (B side, single fp16)
    split_kernel<<<1024, 256>>>(x, th, tlp, NA4);
    convert_kernel<<<1024, 256>>>(w_in, wh, NWIN4);

    // 2) QKV GEMM -> fp16 qkv hi (+ lo for Q cols), Q cols scaled by 1/8
    gemm_mma_split<<<dim3(3 * E_ / 128, M_TOK / 128), 256, GEMM_SMEM>>>(
        th, tlp, wh, b_in, nullptr, qh, ql, M_TOK, 3 * E_, E_, 1, E_, E_);

    // 3) flash attention -> att hi/lo
    attn_mma<<<dim3(T_ / 64, B_ * H_), 128, ATTN_SMEM>>>(qh, ql, ah, al);

    // 4) fused projection weight: Wf = Wc * Wo  (and fused bias)
    //    wh[0..E2)  = Wo^T single fp16 (B of Wf GEMM; overwrites consumed w_in)
    //    wl[0..E2)  = Wc hi,  wl[E2..2E2) = Wc lo  (A of Wf GEMM)
    //    wh[E2..2E2) = Wf single fp16 (output, no lo)
    transpose_convert_kernel<<<dim3(32, 32), dim3(32, 8)>>>(w_out, wh);
    split_kernel<<<1024, 256>>>(w_c, wl, wl + E2_, NW4);
    bias_fuse_kernel<<<E_, 256>>>(w_c, b_out, b_c, biasf);
    gemm_mma_split<<<dim3(E_ / 128, E_ / 128), 256, GEMM_SMEM>>>(
        wl, wl + E2_, wh, zerov, nullptr, wh + E2_, nullptr,
        E_, E_, E_, 1, 0, 0);

    // 5) single fused output GEMM: out = (att_h+att_l) * Wf^T + biasf  (fp32)
    gemm_mma_split<<<dim3(E_ / 128, M_TOK / 128), 256, GEMM_SMEM>>>(
        ah, al, wh + E2_, biasf, out, nullptr, nullptr,
        M_TOK, E_, E_, 0, 0, 0);
}

// round 8
// speedup vs baseline: 6.2704x; 1.5472x over previous
#include <cuda_runtime.h>
#include <cuda_fp16.h>
#include <cstdint>
#include <cstddef>

// Problem constants
#define B_  8
#define T_  1024
#define E_  1024
#define H_  16
#define DH_ 64
#define M_TOK (B_ * T_)        // 8192 tokens
#define E2_ ((size_t)E_ * E_)

// ---------------------------------------------------------------------------
// Scratch (no cudaMalloc allowed -> __device__ globals)
// ---------------------------------------------------------------------------
__device__ __half g_qh[(size_t)M_TOK * 3 * E_];     // 48 MB  qkv hi (k/v single)
__device__ __half g_ql[(size_t)M_TOK * 3 * E_];     // 48 MB  qkv lo (Q cols only)
__device__ __half g_ah[(size_t)M_TOK * E_];         // 16 MB  att (single fp16)
__device__ __half g_th[(size_t)M_TOK * E_];         // 16 MB  x (single fp16)
__device__ __half g_wh[(size_t)3 * E_ * E_];        // 6 MB   w_in / Wo^T+Wf
__device__ __half g_wl[(size_t)2 * E_ * E_];        // 4 MB   Wc single
__device__ float g_biasf[E_];                       // fused bias
__device__ float g_zero[E_];                        // zeros (.bss)

// ---------------------------------------------------------------------------
// PTX helpers (portable sm_80+ only; target is base sm_100)
// ---------------------------------------------------------------------------
__device__ __forceinline__ uint32_t smem_to_u32(const void* p) {
    uint32_t a;
    asm("{ .reg .u64 t; cvta.to.shared.u64 t, %1; cvt.u32.u64 %0, t; }"
        : "=r"(a) : "l"(p));
    return a;
}

#define CP_ASYNC16(dst, src) \
    asm volatile("cp.async.cg.shared.global [%0], [%1], 16;" \
                 :: "r"(dst), "l"(src) : "memory")
#define CP_COMMIT() asm volatile("cp.async.commit_group;" ::: "memory")
#define CP_WAIT(n)  asm volatile("cp.async.wait_group %0;" :: "n"(n) : "memory")

#define LDSM_X4(r, addr) \
    asm volatile("ldmatrix.sync.aligned.m8n8.x4.shared.b16 {%0,%1,%2,%3}, [%4];" \
                 : "=r"((r)[0]), "=r"((r)[1]), "=r"((r)[2]), "=r"((r)[3]) \
                 : "r"(addr))
#define LDSM_X2(r, addr) \
    asm volatile("ldmatrix.sync.aligned.m8n8.x2.shared.b16 {%0,%1}, [%2];" \
                 : "=r"((r)[0]), "=r"((r)[1]) : "r"(addr))
#define LDSM_X2T(r, addr) \
    asm volatile("ldmatrix.sync.aligned.m8n8.x2.trans.shared.b16 {%0,%1}, [%2];" \
                 : "=r"((r)[0]), "=r"((r)[1]) : "r"(addr))

#define MMA_F16(c, a, b0, b1) \
    asm volatile("mma.sync.aligned.m16n8k16.row.col.f32.f16.f16.f32 " \
                 "{%0,%1,%2,%3}, {%4,%5,%6,%7}, {%8,%9}, {%0,%1,%2,%3};" \
                 : "+f"((c)[0]), "+f"((c)[1]), "+f"((c)[2]), "+f"((c)[3]) \
                 : "r"((a)[0]), "r"((a)[1]), "r"((a)[2]), "r"((a)[3]), \
                   "r"(b0), "r"(b1))

__device__ __forceinline__ uint32_t pack_h2(__half a, __half b) {
    __half2 t = __halves2half2(a, b);
    return *reinterpret_cast<uint32_t*>(&t);
}

// split 2 floats into hi/lo fp16x2 words; returns hi, writes lo
__device__ __forceinline__ uint32_t pack_hi2(float x, float y, uint32_t& lo) {
    __half hx = __float2half_rn(x), hy = __float2half_rn(y);
    __half lx = __float2half_rn(x - __half2float(hx));
    __half ly = __float2half_rn(y - __half2float(hy));
    lo = pack_h2(lx, ly);
    return pack_h2(hx, hy);
}

// ---------------------------------------------------------------------------
// fp32 -> single fp16 convert, vectorized
// ---------------------------------------------------------------------------
__global__ void convert_kernel(const float* __restrict__ x,
                               __half* __restrict__ hi, int n4) {
    int i = blockIdx.x * blockDim.x + threadIdx.x;
    int stride = gridDim.x * blockDim.x;
    for (; i < n4; i += stride) {
        float4 v = ((const float4*)x)[i];
        ((uint2*)hi)[i] = make_uint2(
            pack_h2(__float2half_rn(v.x), __float2half_rn(v.y)),
            pack_h2(__float2half_rn(v.z), __float2half_rn(v.w)));
    }
}

// fp32 [E,E] -> transposed single fp16 [E,E] (out[i][j] = in[j][i])
__global__ void transpose_convert_kernel(const float* __restrict__ x,
                                         __half* __restrict__ hi) {
    __shared__ float tile[32][33];
    const int bx = blockIdx.x * 32, by = blockIdx.y * 32;
    const int tx = threadIdx.x, ty = threadIdx.y;     // 32 x 8
#pragma unroll
    for (int u = 0; u < 4; u++)
        tile[ty + u * 8][tx] = x[(size_t)(by + ty + u * 8) * E_ + bx + tx];
    __syncthreads();
#pragma unroll
    for (int u = 0; u < 4; u++) {
        int r = ty + u * 8;
        hi[(size_t)(bx + r) * E_ + by + tx] = __float2half_rn(tile[tx][r]);
    }
}

// fused bias: bf[n] = bc[n] + sum_k bo[k] * Wc[n,k]
__global__ void bias_fuse_kernel(const float* __restrict__ wc,
                                 const float* __restrict__ bo,
                                 const float* __restrict__ bc,
                                 float* __restrict__ bf) {
    __shared__ float red[8];
    const int n = blockIdx.x, tid = threadIdx.x;
    float s = 0.f;
    for (int k = tid; k < E_; k += 256)
        s += wc[(size_t)n * E_ + k] * bo[k];
#pragma unroll
    for (int o = 16; o > 0; o >>= 1) s += __shfl_xor_sync(0xffffffffu, s, o);
    if ((tid & 31) == 0) red[tid >> 5] = s;
    __syncthreads();
    if (tid == 0) {
        float t = 0.f;
#pragma unroll
        for (int w = 0; w < 8; w++) t += red[w];
        bf[n] = t + bc[n];
    }
}

// ---------------------------------------------------------------------------
// single x single fp16 GEMM: C = A * B^T + bias  (fp32 accum)
// A: [M,K] fp16. B: [N,K] fp16.
// out_f16=0 -> Cf fp32;  out_f16=1 -> Ch hi (+ Cl lo for cols < lo_cols).
// cols < scale_cols get *0.125 (exact) -- folds 1/sqrt(dh) into Q.
// Block 128x128, 8 warps (64x32), KC=32, 3-stage cp.async, 1 sync/chunk.
// stage layout: A[0,8K) | B[8K,16K)
// ---------------------------------------------------------------------------
#define KC 32
#define STAGE_B 16384
#define NSTAGE 3
#define GEMM_SMEM (NSTAGE * STAGE_B)   // 49152

__global__ __launch_bounds__(256)
void gemm_mma(const __half* __restrict__ A,
              const __half* __restrict__ Bs,
              const float* __restrict__ bias,
              float* __restrict__ Cf,
              __half* __restrict__ Ch,
              __half* __restrict__ Cl,
              int M, int N, int K, int out_f16, int scale_cols, int lo_cols)
{
    extern __shared__ char smem[];
    const uint32_t sbase = smem_to_u32(smem);
    const int tid  = threadIdx.x;
    const int wid  = tid >> 5;
    const int lane = tid & 31;
    const int warpM = (wid >> 2) * 64;
    const int warpN = (wid & 3) * 32;
    const int rowA = blockIdx.y * 128;
    const int rowB = blockIdx.x * 128;

    float acc[4][4][4];
#pragma unroll
    for (int mt = 0; mt < 4; mt++)
#pragma unroll
        for (int nt = 0; nt < 4; nt++)
#pragma unroll
            for (int r = 0; r < 4; r++) acc[mt][nt][r] = 0.f;

    const int idx0 = tid * 2;
    const int NC = K / KC;

    auto load_stage = [&](int c, int s) {
        const uint32_t sb = sbase + s * STAGE_B;
#pragma unroll
        for (int e = 0; e < 2; e++) {
            int idx  = idx0 + e;
            int row  = idx >> 2;
            int unit = idx & 3;
            uint32_t soff = (uint32_t)(row * 64 + ((unit ^ ((row >> 1) & 3)) << 4));
            size_t goffA = ((size_t)(rowA + row) * K + c * KC + unit * 8) * 2;
            size_t goffB = ((size_t)(rowB + row) * K + c * KC + unit * 8) * 2;
            CP_ASYNC16(sb + soff,        (const char*)A  + goffA);
            CP_ASYNC16(sb + 8192 + soff, (const char*)Bs + goffB);
        }
    };

    load_stage(0, 0);
    CP_COMMIT();
    if (NC > 1) { load_stage(1, 1); CP_COMMIT(); }

    // A ldmatrix x4 lane mapping (16 rows x 2 k-halves)
    const int a_row_in = (lane & 7) + ((lane >> 3) & 1) * 8;
    const int a_ksub   = (lane >> 4);
    // B ldmatrix x4 lane mapping: n-tile pair (16 rows) x 2 k-halves
    const int b_row_in = (lane & 7) + (lane >> 4) * 8;   // row within 16-row pair
    const int b_ksub   = (lane >> 3) & 1;                // k-half select

    for (int c = 0; c < NC; c++) {
        if (c + 1 < NC) CP_WAIT(1); else CP_WAIT(0);
        __syncthreads();

        if (c + 2 < NC) { load_stage(c + 2, (c + 2) % NSTAGE); CP_COMMIT(); }

        const uint32_t sb = sbase + (c % NSTAGE) * STAGE_B;

#pragma unroll
        for (int j = 0; j < 2; j++) {
            uint32_t aF[4][4];
            uint32_t bF[2][4];
            const int aunit = j * 2 + a_ksub;
            const int bunit = j * 2 + b_ksub;
#pragma unroll
            for (int mt = 0; mt < 4; mt++) {
                int row = warpM + mt * 16 + a_row_in;
                uint32_t xo = ((aunit ^ ((row >> 1) & 3)) << 4);
                LDSM_X4(aF[mt], sb + row * 64 + xo);
            }
#pragma unroll
            for (int pr = 0; pr < 2; pr++) {
                int row = warpN + pr * 16 + b_row_in;
                uint32_t xo = ((bunit ^ ((row >> 1) & 3)) << 4);
                LDSM_X4(bF[pr], sb + 8192 + row * 64 + xo);
            }
#pragma unroll
            for (int mt = 0; mt < 4; mt++)
#pragma unroll
                for (int pr = 0; pr < 2; pr++) {
                    MMA_F16(acc[mt][2 * pr],     aF[mt], bF[pr][0], bF[pr][1]);
                    MMA_F16(acc[mt][2 * pr + 1], aF[mt], bF[pr][2], bF[pr][3]);
                }
        }
    }

    // epilogue
    const int erow = lane >> 2;
    const int ecol = (lane & 3) * 2;
#pragma unroll
    for (int mt = 0; mt < 4; mt++) {
#pragma unroll
        for (int nt = 0; nt < 4; nt++) {
            int gr = rowA + warpM + mt * 16 + erow;
            int gc = rowB + warpN + nt * 8 + ecol;
            float b0 = __ldg(bias + gc);
            float b1 = __ldg(bias + gc + 1);
            float sc = (gc < scale_cols) ? 0.125f : 1.0f;
            float v00 = (acc[mt][nt][0] + b0) * sc;
            float v01 = (acc[mt][nt][1] + b1) * sc;
            float v10 = (acc[mt][nt][2] + b0) * sc;
            float v11 = (acc[mt][nt][3] + b1) * sc;
            if (out_f16) {
                uint32_t lo0, lo1, hi0, hi1;
                hi0 = pack_hi2(v00, v01, lo0);
                hi1 = pack_hi2(v10, v11, lo1);
                *(uint32_t*)(Ch + (size_t)gr * N + gc)       = hi0;
                *(uint32_t*)(Ch + (size_t)(gr + 8) * N + gc) = hi1;
                if (gc < lo_cols) {
                    *(uint32_t*)(Cl + (size_t)gr * N + gc)       = lo0;
                    *(uint32_t*)(Cl + (size_t)(gr + 8) * N + gc) = lo1;
                }
            } else {
                *(float2*)(Cf + (size_t)gr * N + gc)       = make_float2(v00, v01);
                *(float2*)(Cf + (size_t)(gr + 8) * N + gc) = make_float2(v10, v11);
            }
        }
    }
}

// ---------------------------------------------------------------------------
// Flash attention, fp16: S = (Qh+Ql)K, O = (Ph+Pl)V (K,V single fp16).
// Output single fp16 (att feeds a single-single GEMM).
// smem: Qh|Ql (16 KB) + 2 stages x (K|V = 16 KB) = 48 KB.
// ---------------------------------------------------------------------------
#define ATTN_SMEM (16384 + 2 * 16384)

__global__ __launch_bounds__(128, 2)
void attn_mma(const __half* __restrict__ qkvh,
              const __half* __restrict__ qkvl,
              __half* __restrict__ oh)
{
    extern __shared__ char smem[];
    const uint32_t sbase = smem_to_u32(smem);
    const int tid  = threadIdx.x;
    const int lane = tid & 31;
    const int warp = tid >> 5;
    const int qt = blockIdx.x;
    const int bh = blockIdx.y;
    const int b = bh >> 4;
    const int h = bh & 15;

    const uint32_t sQh = sbase;
    const uint32_t sQl = sbase + 8192;

    const size_t tok0 = (size_t)b * T_;
    const size_t rs = 3 * E_;

    {
        const __half* qb_h = qkvh + (tok0 + qt * 64) * rs + h * DH_;
        const __half* qb_l = qkvl + (tok0 + qt * 64) * rs + h * DH_;
#pragma unroll
        for (int it = 0; it < 4; it++) {
            int idx = tid + it * 128;
            int row = idx >> 3, unit = idx & 7;
            uint32_t off = (uint32_t)(row * 128 + ((unit ^ (row & 7)) << 4));
            CP_ASYNC16(sQh + off, (const char*)(qb_h + (size_t)row * rs) + unit * 16);
            CP_ASYNC16(sQl + off, (const char*)(qb_l + (size_t)row * rs) + unit * 16);
        }
    }

    auto load_kv = [&](int kt, int s) {
        uint32_t sb = sbase + 16384 + s * 16384;
        const __half* kh = qkvh + (tok0 + kt * 64) * rs + E_ + h * DH_;
#pragma unroll
        for (int it = 0; it < 4; it++) {
            int idx = tid + it * 128;
            int row = idx >> 3, unit = idx & 7;
            uint32_t off = (uint32_t)(row * 128 + ((unit ^ (row & 7)) << 4));
            size_t g = (size_t)row * rs;
            CP_ASYNC16(sb +        off, (const char*)(kh + g) + unit * 16);
            CP_ASYNC16(sb + 8192 + off, (const char*)(kh + E_ + g) + unit * 16);
        }
    };

    load_kv(0, 0);
    CP_COMMIT();

    const int tl   = lane & 15;
    const int arow = warp * 16 + tl;
    const int aun  = lane >> 4;
    const int brw  = tl & 7;
    const int bks  = (tl >> 3) & 1;

    float O[8][4];
#pragma unroll
    for (int t = 0; t < 8; t++)
#pragma unroll
        for (int r = 0; r < 4; r++) O[t][r] = 0.f;
    float m0 = -1e30f, m1 = -1e30f, l0 = 0.f, l1 = 0.f;

    uint32_t qH[4][4], qL[4][4];
    bool qloaded = false;

    for (int kt = 0; kt <= qt; kt++) {
        CP_WAIT(0);
        __syncthreads();
        if (kt < qt) { load_kv(kt + 1, (kt + 1) & 1); CP_COMMIT(); }

        if (!qloaded) {
            qloaded = true;
#pragma unroll
            for (int j = 0; j < 4; j++) {
                int au = j * 2 + aun;
                uint32_t aoff = (uint32_t)(arow * 128 + ((au ^ (arow & 7)) << 4));
                LDSM_X4(qH[j], sQh + aoff);
                LDSM_X4(qL[j], sQl + aoff);
            }
        }

        const uint32_t sb = sbase + 16384 + (kt & 1) * 16384;
        const uint32_t sK = sb, sV = sb + 8192;

        float S[8][4];
#pragma unroll
        for (int t = 0; t < 8; t++)
#pragma unroll
            for (int r = 0; r < 4; r++) S[t][r] = 0.f;

#pragma unroll
        for (int j = 0; j < 4; j++) {
#pragma unroll
            for (int t = 0; t < 8; t++) {
                int r = t * 8 + brw;
                int u = j * 2 + bks;
                uint32_t boff = (uint32_t)(r * 128 + ((u ^ (r & 7)) << 4));
                uint32_t bF[2];
                LDSM_X2(bF, sK + boff);
                MMA_F16(S[t], qH[j], bF[0], bF[1]);
                MMA_F16(S[t], qL[j], bF[0], bF[1]);
            }
        }

        if (kt == qt) {
            int r0 = warp * 16 + (lane >> 2);
#pragma unroll
            for (int t = 0; t < 8; t++) {
                int c = t * 8 + (lane & 3) * 2;
                if (c     > r0)     S[t][0] = -1e30f;
                if (c + 1 > r0)     S[t][1] = -1e30f;
                if (c     > r0 + 8) S[t][2] = -1e30f;
                if (c + 1 > r0 + 8) S[t][3] = -1e30f;
            }
        }

        float rm0 = -1e30f, rm1 = -1e30f;
#pragma unroll
        for (int t = 0; t < 8; t++) {
            rm0 = fmaxf(rm0, fmaxf(S[t][0], S[t][1]));
            rm1 = fmaxf(rm1, fmaxf(S[t][2], S[t][3]));
        }
        rm0 = fmaxf(rm0, __shfl_xor_sync(0xffffffffu, rm0, 1));
        rm0 = fmaxf(rm0, __shfl_xor_sync(0xffffffffu, rm0, 2));
        rm1 = fmaxf(rm1, __shfl_xor_sync(0xffffffffu, rm1, 1));
        rm1 = fmaxf(rm1, __shfl_xor_sync(0xffffffffu, rm1, 2));
        float mn0 = fmaxf(m0, rm0), mn1 = fmaxf(m1, rm1);
        float al0 = __expf(m0 - mn0), al1 = __expf(m1 - mn1);
        m0 = mn0; m1 = mn1;

        float ls0 = 0.f, ls1 = 0.f;
#pragma unroll
        for (int t = 0; t < 8; t++) {
            S[t][0] = __expf(S[t][0] - mn0); ls0 += S[t][0];
            S[t][1] = __expf(S[t][1] - mn0); ls0 += S[t][1];
            S[t][2] = __expf(S[t][2] - mn1); ls1 += S[t][2];
            S[t][3] = __expf(S[t][3] - mn1); ls1 += S[t][3];
        }
        l0 = l0 * al0 + ls0;
        l1 = l1 * al1 + ls1;
#pragma unroll
        for (int t = 0; t < 8; t++) {
            O[t][0] *= al0; O[t][1] *= al0;
            O[t][2] *= al1; O[t][3] *= al1;
        }

        uint32_t pH[4][4], pL[4][4];
#pragma unroll
        for (int j = 0; j < 4; j++) {
            pH[j][0] = pack_hi2(S[2*j][0],   S[2*j][1],   pL[j][0]);
            pH[j][1] = pack_hi2(S[2*j][2],   S[2*j][3],   pL[j][1]);
            pH[j][2] = pack_hi2(S[2*j+1][0], S[2*j+1][1], pL[j][2]);
            pH[j][3] = pack_hi2(S[2*j+1][2], S[2*j+1][3], pL[j][3]);
        }

#pragma unroll
        for (int j = 0; j < 4; j++) {
            int vr = j * 16 + brw + bks * 8;
#pragma unroll
            for (int t = 0; t < 8; t++) {
                uint32_t voff = (uint32_t)(vr * 128 + ((t ^ (vr & 7)) << 4));
                uint32_t vF[2];
                LDSM_X2T(vF, sV + voff);
                MMA_F16(O[t], pH[j], vF[0], vF[1]);
                MMA_F16(O[t], pL[j], vF[0], vF[1]);
            }
        }
    }

    l0 += __shfl_xor_sync(0xffffffffu, l0, 1);
    l0 += __shfl_xor_sync(0xffffffffu, l0, 2);
    l1 += __shfl_xor_sync(0xffffffffu, l1, 1);
    l1 += __shfl_xor_sync(0xffffffffu, l1, 2);
    float inv0 = 1.f / l0, inv1 = 1.f / l1;

    int r0 = qt * 64 + warp * 16 + (lane >> 2);
    size_t grow0 = (tok0 + r0) * E_ + h * DH_;
    size_t grow1 = grow0 + (size_t)8 * E_;
#pragma unroll
    for (int t = 0; t < 8; t++) {
        int c = t * 8 + (lane & 3) * 2;
        *(uint32_t*)(oh + grow0 + c) =
            pack_h2(__float2half_rn(O[t][0] * inv0), __float2half_rn(O[t][1] * inv0));
        *(uint32_t*)(oh + grow1 + c) =
            pack_h2(__float2half_rn(O[t][2] * inv1), __float2half_rn(O[t][3] * inv1));
    }
}

// ---------------------------------------------------------------------------
// kernel_launch
// inputs: x, in_proj_w, in_proj_b, out_proj_w, out_proj_b, c_proj_w, c_proj_b
// ---------------------------------------------------------------------------
extern "C" void kernel_launch(void* const* d_in, const int* in_sizes, int n_in,
                              void* d_out, int out_size)
{
    const float* x     = (const float*)d_in[0];
    const float* w_in  = (const float*)d_in[1];
    const float* b_in  = (const float*)d_in[2];
    const float* w_out = (const float*)d_in[3];
    const float* b_out = (const float*)d_in[4];
    const float* w_c   = (const float*)d_in[5];
    const float* b_c   = (const float*)d_in[6];
    float* out = (float*)d_out;

    __half *qh, *ql, *ah, *th, *wh, *wl;
    float *biasf, *zerov;
    cudaGetSymbolAddress((void**)&qh, g_qh);
    cudaGetSymbolAddress((void**)&ql, g_ql);
    cudaGetSymbolAddress((void**)&ah, g_ah);
    cudaGetSymbolAddress((void**)&th, g_th);
    cudaGetSymbolAddress((void**)&wh, g_wh);
    cudaGetSymbolAddress((void**)&wl, g_wl);
    cudaGetSymbolAddress((void**)&biasf, g_biasf);
    cudaGetSymbolAddress((void**)&zerov, g_zero);

    cudaFuncSetAttribute(gemm_mma,
                         cudaFuncAttributeMaxDynamicSharedMemorySize, GEMM_SMEM);
    cudaFuncSetAttribute(attn_mma,
                         cudaFuncAttributeMaxDynamicSharedMemorySize, ATTN_SMEM);

    const int NA4   = M_TOK * E_ / 4;
    const int NWIN4 = 3 * E_ * E_ / 4;
    const int NW4   = E_ * E_ / 4;

    // 1) convert x and in_proj_w to fp16
    convert_kernel<<<1024, 256>>>(x, th, NA4);
    convert_kernel<<<1024, 256>>>(w_in, wh, NWIN4);

    // 2) QKV GEMM -> fp16 qkv hi (+ lo for Q cols), Q cols scaled by 1/8
    gemm_mma<<<dim3(3 * E_ / 128, M_TOK / 128), 256, GEMM_SMEM>>>(
        th, wh, b_in, nullptr, qh, ql, M_TOK, 3 * E_, E_, 1, E_, E_);

    // 3) flash attention -> att single fp16
    attn_mma<<<dim3(T_ / 64, B_ * H_), 128, ATTN_SMEM>>>(qh, ql, ah);

    // 4) fused projection weight: Wf = Wc * Wo  (and fused bias)
    //    wh[0..E2)   = Wo^T single fp16 (w_in consumed)
    //    wl[0..E2)   = Wc single fp16
    //    wh[E2..2E2) = Wf single fp16
    transpose_convert_kernel<<<dim3(32, 32), dim3(32, 8)>>>(w_out, wh);
    convert_kernel<<<1024, 256>>>(w_c, wl, NW4);
    bias_fuse_kernel<<<E_, 256>>>(w_c, b_out, b_c, biasf);
    gemm_mma<<<dim3(E_ / 128, E_ / 128), 256, GEMM_SMEM>>>(
        wl, wh, zerov, nullptr, wh + E2_, nullptr, E_, E_, E_, 1, 0, 0);

    // 5) single fused output GEMM: out = att * Wf^T + biasf  (fp32)
    gemm_mma<<<dim3(E_ / 128, M_TOK / 128), 256, GEMM_SMEM>>>(
        ah, wh + E2_, biasf, out, nullptr, nullptr, M_TOK, E_, E_, 0, 0, 0);
}